// round 3
// baseline (speedup 1.0000x reference)
#include <cuda_runtime.h>
#include <math.h>
#include <stdint.h>

#define N_NODES 100000
#define IN_DIM 128
#define HID 128
#define OUT_DIM 64

// ---------------- scratch (device globals; no allocation allowed) -----------
__device__ float g_h1[(size_t)N_NODES * HID];       // x @ W1
__device__ float g_agg1[(size_t)N_NODES * HID];     // aggregated layer1 (then relu'd in place)
__device__ float g_h2[(size_t)N_NODES * OUT_DIM];   // hr @ W2
__device__ float g_agg2[(size_t)N_NODES * OUT_DIM]; // aggregated layer2
__device__ float g_dinv[N_NODES];
__device__ int   g_deg[N_NODES];

// ---------------- zero scratch ----------------------------------------------
__global__ void zero_kernel() {
    size_t i = (size_t)blockIdx.x * blockDim.x + threadIdx.x;
    size_t stride = (size_t)gridDim.x * blockDim.x;
    const size_t n1 = (size_t)N_NODES * HID;
    const size_t n2 = (size_t)N_NODES * OUT_DIM;
    for (size_t k = i; k < n1; k += stride) g_agg1[k] = 0.0f;
    for (size_t k = i; k < n2; k += stride) g_agg2[k] = 0.0f;
    for (size_t k = i; k < N_NODES; k += stride) g_deg[k] = 0;
}

// ---------------- degree + dinv ---------------------------------------------
__global__ void degree_kernel(const int* __restrict__ dst, int E) {
    int i = blockIdx.x * blockDim.x + threadIdx.x;
    if (i < E) atomicAdd(&g_deg[dst[i]], 1);
}

__global__ void dinv_kernel() {
    int v = blockIdx.x * blockDim.x + threadIdx.x;
    if (v < N_NODES) {
        float deg = (float)(g_deg[v] + 1);  // +1 self loop, always > 0
        g_dinv[v] = rsqrtf(deg);
    }
}

// ---------------- SGEMM: C[M,N] = A[M,K=128] * B[128,N] ---------------------
// BM=32 rows per block, full N per block. 256 threads: tx in [0,32) covers
// TN=N/32 cols each, ty in [0,8) covers 4 rows each.
template <int N>
__global__ void gemm_kernel(const float* __restrict__ A,
                            const float* __restrict__ B,
                            float* __restrict__ C, int M) {
    constexpr int K = 128;
    constexpr int BM = 32;
    constexpr int BK = 32;
    constexpr int TN = N / 32;  // 4 for N=128, 2 for N=64

    __shared__ float As[BM][BK + 1];
    __shared__ float Bs[BK][N];

    int tid = threadIdx.x;
    int tx = tid & 31;        // col group
    int ty = tid >> 5;        // row group (0..7)
    int row0 = blockIdx.x * BM;

    float acc[4][TN];
#pragma unroll
    for (int i = 0; i < 4; i++)
#pragma unroll
        for (int j = 0; j < TN; j++) acc[i][j] = 0.0f;

    for (int k0 = 0; k0 < K; k0 += BK) {
        // load A tile: 32x32 = 1024 elems, 4 per thread
#pragma unroll
        for (int l = 0; l < 4; l++) {
            int e = tid + l * 256;
            int r = e >> 5, c = e & 31;
            int gr = row0 + r;
            As[r][c] = (gr < M) ? A[(size_t)gr * K + k0 + c] : 0.0f;
        }
        // load B tile: 32xN elems, (32*N/256) per thread
#pragma unroll
        for (int l = 0; l < (BK * N) / 256; l++) {
            int e = tid + l * 256;
            int r = e / N, c = e % N;
            Bs[r][c] = B[(size_t)(k0 + r) * N + c];
        }
        __syncthreads();

#pragma unroll
        for (int kk = 0; kk < BK; kk++) {
            float a[4];
#pragma unroll
            for (int i = 0; i < 4; i++) a[i] = As[ty * 4 + i][kk];
#pragma unroll
            for (int j = 0; j < TN; j++) {
                float b = Bs[kk][tx * TN + j];
#pragma unroll
                for (int i = 0; i < 4; i++) acc[i][j] += a[i] * b;
            }
        }
        __syncthreads();
    }

#pragma unroll
    for (int i = 0; i < 4; i++) {
        int gr = row0 + ty * 4 + i;
        if (gr < M) {
#pragma unroll
            for (int j = 0; j < TN; j++)
                C[(size_t)gr * N + tx * TN + j] = acc[i][j];
        }
    }
}

// ---------------- edge scatter, 128 cols: 1 warp per edge -------------------
__global__ void scatter128_kernel(const float* __restrict__ h,
                                  const int* __restrict__ src,
                                  const int* __restrict__ dst,
                                  float* __restrict__ agg, int E) {
    int w = (blockIdx.x * blockDim.x + threadIdx.x) >> 5;
    int lane = threadIdx.x & 31;
    if (w >= E) return;
    int s = src[w];
    int d = dst[w];
    float coef = g_dinv[s] * g_dinv[d];
    float4 v = ((const float4*)(h + (size_t)s * 128))[lane];
    float* ap = agg + (size_t)d * 128 + lane * 4;
    atomicAdd(ap + 0, v.x * coef);
    atomicAdd(ap + 1, v.y * coef);
    atomicAdd(ap + 2, v.z * coef);
    atomicAdd(ap + 3, v.w * coef);
}

// ---------------- edge scatter, 64 cols: 2 edges per warp -------------------
__global__ void scatter64_kernel(const float* __restrict__ h,
                                 const int* __restrict__ src,
                                 const int* __restrict__ dst,
                                 float* __restrict__ agg, int E) {
    int w = (blockIdx.x * blockDim.x + threadIdx.x) >> 5;
    int lane = threadIdx.x & 31;
    long long e = (long long)w * 2 + (lane >> 4);
    if (e >= E) return;
    int sub = lane & 15;
    int s = src[e];
    int d = dst[e];
    float coef = g_dinv[s] * g_dinv[d];
    float4 v = ((const float4*)(h + (size_t)s * 64))[sub];
    float* ap = agg + (size_t)d * 64 + sub * 4;
    atomicAdd(ap + 0, v.x * coef);
    atomicAdd(ap + 1, v.y * coef);
    atomicAdd(ap + 2, v.z * coef);
    atomicAdd(ap + 3, v.w * coef);
}

// ---------------- self-loop + bias + relu (in place into agg1) --------------
__global__ void bias_relu_kernel(const float* __restrict__ b1) {
    size_t i = (size_t)blockIdx.x * blockDim.x + threadIdx.x;
    const size_t n = (size_t)N_NODES * HID;
    if (i >= n) return;
    int v = (int)(i >> 7);      // /128
    int c = (int)(i & 127);
    float di = g_dinv[v];
    float val = g_agg1[i] + g_h1[i] * di * di + b1[c];
    g_agg1[i] = fmaxf(val, 0.0f);
}

// ---------------- self-loop + bias + log_softmax -> out ---------------------
// one warp per row (64 cols -> 2 per lane)
__global__ void final_kernel(const float* __restrict__ b2,
                             float* __restrict__ out) {
    int w = (blockIdx.x * blockDim.x + threadIdx.x) >> 5;
    int lane = threadIdx.x & 31;
    if (w >= N_NODES) return;
    float di = g_dinv[w];
    float d2 = di * di;
    size_t base = (size_t)w * 64;
    float v0 = g_agg2[base + lane] + g_h2[base + lane] * d2 + b2[lane];
    float v1 = g_agg2[base + lane + 32] + g_h2[base + lane + 32] * d2 + b2[lane + 32];
    float m = fmaxf(v0, v1);
#pragma unroll
    for (int o = 16; o > 0; o >>= 1)
        m = fmaxf(m, __shfl_xor_sync(0xFFFFFFFF, m, o));
    float s = __expf(v0 - m) + __expf(v1 - m);
#pragma unroll
    for (int o = 16; o > 0; o >>= 1)
        s += __shfl_xor_sync(0xFFFFFFFF, s, o);
    float lse = m + logf(s);
    out[base + lane] = v0 - lse;
    out[base + lane + 32] = v1 - lse;
}

// ---------------- launch -----------------------------------------------------
extern "C" void kernel_launch(void* const* d_in, const int* in_sizes, int n_in,
                              void* d_out, int out_size) {
    const float* x = (const float*)d_in[0];
    const int* ei = (const int*)d_in[1];
    const float* W1 = (const float*)d_in[2];
    const float* b1 = (const float*)d_in[3];
    const float* W2 = (const float*)d_in[4];
    const float* b2 = (const float*)d_in[5];
    float* out = (float*)d_out;

    int E = in_sizes[1] / 2;
    const int* src = ei;
    const int* dst = ei + E;

    // device pointers to scratch (resolved via symbols inside kernels)
    float* h1;  cudaGetSymbolAddress((void**)&h1, g_h1);
    float* agg1; cudaGetSymbolAddress((void**)&agg1, g_agg1);
    float* h2;  cudaGetSymbolAddress((void**)&h2, g_h2);
    float* agg2; cudaGetSymbolAddress((void**)&agg2, g_agg2);

    zero_kernel<<<2048, 256>>>();
    degree_kernel<<<(E + 255) / 256, 256>>>(dst, E);
    dinv_kernel<<<(N_NODES + 255) / 256, 256>>>();

    // layer 1
    gemm_kernel<HID><<<(N_NODES + 31) / 32, 256>>>(x, W1, h1, N_NODES);
    {
        long long threads = (long long)E * 32;
        int blocks = (int)((threads + 255) / 256);
        scatter128_kernel<<<blocks, 256>>>(h1, src, dst, agg1, E);
    }
    bias_relu_kernel<<<((size_t)N_NODES * HID + 255) / 256, 256>>>(b1);

    // layer 2
    gemm_kernel<OUT_DIM><<<(N_NODES + 31) / 32, 256>>>(agg1, W2, h2, N_NODES);
    {
        long long warps = ((long long)E + 1) / 2;
        long long threads = warps * 32;
        int blocks = (int)((threads + 255) / 256);
        scatter64_kernel<<<blocks, 256>>>(h2, src, dst, agg2, E);
    }
    final_kernel<<<(N_NODES * 32 + 255) / 256, 256>>>(b2, out);
}

// round 5
// speedup vs baseline: 1.9169x; 1.9169x over previous
#include <cuda_runtime.h>
#include <math.h>
#include <stdint.h>

#define N_NODES 100000
#define E_MAX   1600000
#define IN_DIM 128
#define HID 128
#define OUT_DIM 64

// ---------------- scratch (device globals; no allocation allowed) -----------
__device__ float g_h1[(size_t)N_NODES * HID];       // x @ W1
__device__ float g_hr[(size_t)N_NODES * HID];       // relu(aggregated layer1)
__device__ float g_h2[(size_t)N_NODES * OUT_DIM];   // hr @ W2
__device__ float g_dinv[N_NODES];
__device__ int   g_deg[N_NODES];
__device__ int   g_rowstart[N_NODES + 1];
__device__ int   g_cursor[N_NODES];
__device__ int   g_csr_src[E_MAX];

// ---------------- zero degree ------------------------------------------------
__global__ void zero_deg_kernel() {
    int i = blockIdx.x * blockDim.x + threadIdx.x;
    if (i < N_NODES) g_deg[i] = 0;
}

// ---------------- degree ------------------------------------------------------
__global__ void degree_kernel(const int* __restrict__ dst, int E) {
    int i = blockIdx.x * blockDim.x + threadIdx.x;
    if (i < E) atomicAdd(&g_deg[dst[i]], 1);
}

// ---------------- dinv --------------------------------------------------------
__global__ void dinv_kernel() {
    int v = blockIdx.x * blockDim.x + threadIdx.x;
    if (v < N_NODES) {
        float deg = (float)(g_deg[v] + 1);  // +1 self loop -> always > 0
        g_dinv[v] = rsqrtf(deg);
    }
}

// ---------------- single-block exclusive scan of deg -> rowstart, cursor -----
__global__ void scan_kernel() {
    const int T = 1024;
    __shared__ int sh[T];
    int tid = threadIdx.x;
    const int CH = (N_NODES + T - 1) / T;  // 98
    int base = tid * CH;
    int s = 0;
    for (int i = 0; i < CH; i++) {
        int idx = base + i;
        if (idx < N_NODES) s += g_deg[idx];
    }
    sh[tid] = s;
    __syncthreads();
    // Hillis-Steele inclusive scan
    for (int off = 1; off < T; off <<= 1) {
        int v = (tid >= off) ? sh[tid - off] : 0;
        __syncthreads();
        sh[tid] += v;
        __syncthreads();
    }
    int run = sh[tid] - s;  // exclusive prefix for this chunk
    for (int i = 0; i < CH; i++) {
        int idx = base + i;
        if (idx < N_NODES) {
            g_rowstart[idx] = run;
            g_cursor[idx] = run;
            run += g_deg[idx];
        }
    }
    if (tid == T - 1) g_rowstart[N_NODES] = sh[T - 1];
}

// ---------------- counting-sort fill: group edge srcs by dst ------------------
__global__ void fill_kernel(const int* __restrict__ src,
                            const int* __restrict__ dst, int E) {
    int i = blockIdx.x * blockDim.x + threadIdx.x;
    if (i < E) {
        int d = dst[i];
        int p = atomicAdd(&g_cursor[d], 1);
        g_csr_src[p] = src[i];
    }
}

// ---------------- SGEMM: C[M,N] = A[M,K=128] * B[128,N] ----------------------
template <int N>
__global__ void gemm_kernel(const float* __restrict__ A,
                            const float* __restrict__ B,
                            float* __restrict__ C, int M) {
    constexpr int K = 128;
    constexpr int BM = 32;
    constexpr int BK = 32;
    constexpr int TN = N / 32;  // 4 for N=128, 2 for N=64

    __shared__ float As[BM][BK + 1];
    __shared__ float Bs[BK][N];

    int tid = threadIdx.x;
    int tx = tid & 31;
    int ty = tid >> 5;
    int row0 = blockIdx.x * BM;

    float acc[4][TN];
#pragma unroll
    for (int i = 0; i < 4; i++)
#pragma unroll
        for (int j = 0; j < TN; j++) acc[i][j] = 0.0f;

    for (int k0 = 0; k0 < K; k0 += BK) {
#pragma unroll
        for (int l = 0; l < 4; l++) {
            int e = tid + l * 256;
            int r = e >> 5, c = e & 31;
            int gr = row0 + r;
            As[r][c] = (gr < M) ? A[(size_t)gr * K + k0 + c] : 0.0f;
        }
#pragma unroll
        for (int l = 0; l < (BK * N) / 256; l++) {
            int e = tid + l * 256;
            int r = e / N, c = e % N;
            Bs[r][c] = B[(size_t)(k0 + r) * N + c];
        }
        __syncthreads();

#pragma unroll
        for (int kk = 0; kk < BK; kk++) {
            float a[4];
#pragma unroll
            for (int i = 0; i < 4; i++) a[i] = As[ty * 4 + i][kk];
#pragma unroll
            for (int j = 0; j < TN; j++) {
                float b = Bs[kk][tx * TN + j];
#pragma unroll
                for (int i = 0; i < 4; i++) acc[i][j] += a[i] * b;
            }
        }
        __syncthreads();
    }

#pragma unroll
    for (int i = 0; i < 4; i++) {
        int gr = row0 + ty * 4 + i;
        if (gr < M) {
#pragma unroll
            for (int j = 0; j < TN; j++)
                C[(size_t)gr * N + tx * TN + j] = acc[i][j];
        }
    }
}

// ---------------- layer1 pull-aggregation: warp per node, 128 cols -----------
// hr[v] = relu( dinv[v]*(sum_s dinv[s]*h1[s]) + dinv[v]^2*h1[v] + b1 )
__global__ void agg128_kernel(const float* __restrict__ h,
                              const float* __restrict__ b1,
                              float* __restrict__ hr) {
    int v = (blockIdx.x * blockDim.x + threadIdx.x) >> 5;
    int lane = threadIdx.x & 31;
    if (v >= N_NODES) return;

    int beg = g_rowstart[v];
    int end = g_rowstart[v + 1];

    float4 acc = make_float4(0.f, 0.f, 0.f, 0.f);
    int e = beg;
    for (; e + 2 <= end; e += 2) {
        int s0 = g_csr_src[e];
        int s1 = g_csr_src[e + 1];
        float c0 = g_dinv[s0];
        float c1 = g_dinv[s1];
        float4 v0 = ((const float4*)(h + (size_t)s0 * 128))[lane];
        float4 v1 = ((const float4*)(h + (size_t)s1 * 128))[lane];
        acc.x += v0.x * c0 + v1.x * c1;
        acc.y += v0.y * c0 + v1.y * c1;
        acc.z += v0.z * c0 + v1.z * c1;
        acc.w += v0.w * c0 + v1.w * c1;
    }
    if (e < end) {
        int s0 = g_csr_src[e];
        float c0 = g_dinv[s0];
        float4 v0 = ((const float4*)(h + (size_t)s0 * 128))[lane];
        acc.x += v0.x * c0;
        acc.y += v0.y * c0;
        acc.z += v0.z * c0;
        acc.w += v0.w * c0;
    }

    float dv = g_dinv[v];
    float4 self = ((const float4*)(h + (size_t)v * 128))[lane];
    float4 bb = ((const float4*)b1)[lane];
    float4 r;
    r.x = fmaxf((acc.x + self.x * dv) * dv + bb.x, 0.f);
    r.y = fmaxf((acc.y + self.y * dv) * dv + bb.y, 0.f);
    r.z = fmaxf((acc.z + self.z * dv) * dv + bb.z, 0.f);
    r.w = fmaxf((acc.w + self.w * dv) * dv + bb.w, 0.f);
    ((float4*)(hr + (size_t)v * 128))[lane] = r;
}

// ---------------- layer2 pull-aggregation + log_softmax: warp per node -------
// cols: lane handles 2*lane, 2*lane+1
__global__ void agg64_final_kernel(const float* __restrict__ h,
                                   const float* __restrict__ b2,
                                   float* __restrict__ out) {
    int v = (blockIdx.x * blockDim.x + threadIdx.x) >> 5;
    int lane = threadIdx.x & 31;
    if (v >= N_NODES) return;

    int beg = g_rowstart[v];
    int end = g_rowstart[v + 1];

    float2 acc = make_float2(0.f, 0.f);
    int e = beg;
    for (; e + 2 <= end; e += 2) {
        int s0 = g_csr_src[e];
        int s1 = g_csr_src[e + 1];
        float c0 = g_dinv[s0];
        float c1 = g_dinv[s1];
        float2 v0 = ((const float2*)(h + (size_t)s0 * 64))[lane];
        float2 v1 = ((const float2*)(h + (size_t)s1 * 64))[lane];
        acc.x += v0.x * c0 + v1.x * c1;
        acc.y += v0.y * c0 + v1.y * c1;
    }
    if (e < end) {
        int s0 = g_csr_src[e];
        float c0 = g_dinv[s0];
        float2 v0 = ((const float2*)(h + (size_t)s0 * 64))[lane];
        acc.x += v0.x * c0;
        acc.y += v0.y * c0;
    }

    float dv = g_dinv[v];
    float2 self = ((const float2*)(h + (size_t)v * 64))[lane];
    float2 bb = ((const float2*)b2)[lane];
    float v0 = (acc.x + self.x * dv) * dv + bb.x;
    float v1 = (acc.y + self.y * dv) * dv + bb.y;

    float m = fmaxf(v0, v1);
#pragma unroll
    for (int o = 16; o > 0; o >>= 1)
        m = fmaxf(m, __shfl_xor_sync(0xFFFFFFFF, m, o));
    float s = __expf(v0 - m) + __expf(v1 - m);
#pragma unroll
    for (int o = 16; o > 0; o >>= 1)
        s += __shfl_xor_sync(0xFFFFFFFF, s, o);
    float lse = m + logf(s);
    ((float2*)(out + (size_t)v * 64))[lane] = make_float2(v0 - lse, v1 - lse);
}

// ---------------- launch ------------------------------------------------------
extern "C" void kernel_launch(void* const* d_in, const int* in_sizes, int n_in,
                              void* d_out, int out_size) {
    const float* x = (const float*)d_in[0];
    const int* ei = (const int*)d_in[1];
    const float* W1 = (const float*)d_in[2];
    const float* b1 = (const float*)d_in[3];
    const float* W2 = (const float*)d_in[4];
    const float* b2 = (const float*)d_in[5];
    float* out = (float*)d_out;

    int E = in_sizes[1] / 2;
    const int* src = ei;
    const int* dst = ei + E;

    float* h1; cudaGetSymbolAddress((void**)&h1, g_h1);
    float* hr; cudaGetSymbolAddress((void**)&hr, g_hr);
    float* h2; cudaGetSymbolAddress((void**)&h2, g_h2);

    // graph prep: CSR by destination (no fp atomics anywhere)
    zero_deg_kernel<<<(N_NODES + 255) / 256, 256>>>();
    degree_kernel<<<(E + 255) / 256, 256>>>(dst, E);
    scan_kernel<<<1, 1024>>>();
    dinv_kernel<<<(N_NODES + 255) / 256, 256>>>();
    fill_kernel<<<(E + 255) / 256, 256>>>(src, dst, E);

    // layer 1: transform then pull-aggregate (+bias+relu fused)
    gemm_kernel<HID><<<(N_NODES + 31) / 32, 256>>>(x, W1, h1, N_NODES);
    agg128_kernel<<<(N_NODES * 32 + 255) / 256, 256>>>(h1, b1, hr);

    // layer 2: transform then pull-aggregate (+bias+log_softmax fused)
    gemm_kernel<OUT_DIM><<<(N_NODES + 31) / 32, 256>>>(hr, W2, h2, N_NODES);
    agg64_final_kernel<<<(N_NODES * 32 + 255) / 256, 256>>>(h2, b2, out);
}

// round 6
// speedup vs baseline: 2.0000x; 1.0434x over previous
#include <cuda_runtime.h>
#include <math.h>
#include <stdint.h>

#define N_NODES 100000
#define E_MAX   1600000
#define IN_DIM 128
#define HID 128
#define OUT_DIM 64

// ---------------- scratch (device globals; no allocation allowed) -----------
__device__ float g_h1[(size_t)N_NODES * HID];       // x @ W1
__device__ float g_hr[(size_t)N_NODES * HID];       // relu(aggregated layer1)
__device__ float g_h2[(size_t)N_NODES * OUT_DIM];   // hr @ W2
__device__ float g_dinv[N_NODES];
__device__ int   g_deg[N_NODES];
__device__ int   g_rowstart[N_NODES + 1];
__device__ int   g_cursor[N_NODES];
__device__ int   g_csr_src[E_MAX];

// ---------------- zero degree ------------------------------------------------
__global__ void zero_deg_kernel() {
    int i = blockIdx.x * blockDim.x + threadIdx.x;
    if (i < N_NODES) g_deg[i] = 0;
}

// ---------------- degree ------------------------------------------------------
__global__ void degree_kernel(const int* __restrict__ dst, int E) {
    int i = blockIdx.x * blockDim.x + threadIdx.x;
    if (i < E) atomicAdd(&g_deg[dst[i]], 1);
}

// ---------------- dinv --------------------------------------------------------
__global__ void dinv_kernel() {
    int v = blockIdx.x * blockDim.x + threadIdx.x;
    if (v < N_NODES) {
        float deg = (float)(g_deg[v] + 1);  // +1 self loop -> always > 0
        g_dinv[v] = rsqrtf(deg);
    }
}

// ---------------- single-block exclusive scan of deg -> rowstart, cursor -----
__global__ void scan_kernel() {
    const int T = 1024;
    __shared__ int sh[T];
    int tid = threadIdx.x;
    const int CH = (N_NODES + T - 1) / T;  // 98
    int base = tid * CH;
    int s = 0;
    for (int i = 0; i < CH; i++) {
        int idx = base + i;
        if (idx < N_NODES) s += g_deg[idx];
    }
    sh[tid] = s;
    __syncthreads();
    for (int off = 1; off < T; off <<= 1) {
        int v = (tid >= off) ? sh[tid - off] : 0;
        __syncthreads();
        sh[tid] += v;
        __syncthreads();
    }
    int run = sh[tid] - s;  // exclusive prefix for this chunk
    for (int i = 0; i < CH; i++) {
        int idx = base + i;
        if (idx < N_NODES) {
            g_rowstart[idx] = run;
            g_cursor[idx] = run;
            run += g_deg[idx];
        }
    }
    if (tid == T - 1) g_rowstart[N_NODES] = sh[T - 1];
}

// ---------------- counting-sort fill: group edge srcs by dst ------------------
__global__ void fill_kernel(const int* __restrict__ src,
                            const int* __restrict__ dst, int E) {
    int i = blockIdx.x * blockDim.x + threadIdx.x;
    if (i < E) {
        int d = dst[i];
        int p = atomicAdd(&g_cursor[d], 1);
        g_csr_src[p] = src[i];
    }
}

// ---------------- SGEMM: C[M,N] = A[M,K=128] * B[128,N] ----------------------
// BM=64 rows/block, full N, BK=32. 256 threads: tx in [0,32) covers TN=N/32
// cols, ty in [0,8) covers 8 rows each (TM=8).
template <int N>
__global__ void __launch_bounds__(256) gemm_kernel(
        const float* __restrict__ A,
        const float* __restrict__ B,
        float* __restrict__ C, int M) {
    constexpr int K = 128;
    constexpr int BM = 64;
    constexpr int BK = 32;
    constexpr int TN = N / 32;  // 4 for N=128, 2 for N=64
    constexpr int TM = 8;

    __shared__ float As[BM][BK + 1];
    __shared__ float Bs[BK][N];

    int tid = threadIdx.x;
    int tx = tid & 31;
    int ty = tid >> 5;        // 0..7
    int row0 = blockIdx.x * BM;

    float acc[TM][TN];
#pragma unroll
    for (int i = 0; i < TM; i++)
#pragma unroll
        for (int j = 0; j < TN; j++) acc[i][j] = 0.0f;

    for (int k0 = 0; k0 < K; k0 += BK) {
        // A tile: 64x32 = 2048 scalars, 8 per thread, coalesced
#pragma unroll
        for (int l = 0; l < 8; l++) {
            int e = tid + l * 256;
            int r = e >> 5, c = e & 31;
            int gr = row0 + r;
            As[r][c] = (gr < M) ? A[(size_t)gr * K + k0 + c] : 0.0f;
        }
        // B tile: 32xN floats as float4
#pragma unroll
        for (int l = 0; l < (BK * N) / (256 * 4); l++) {
            int e = tid + l * 256;            // float4 index
            int r = e / (N / 4), c = e % (N / 4);
            ((float4*)&Bs[r][0])[c] = ((const float4*)&B[(size_t)(k0 + r) * N])[c];
        }
        __syncthreads();

#pragma unroll
        for (int kk = 0; kk < BK; kk++) {
            float a[TM];
#pragma unroll
            for (int i = 0; i < TM; i++) a[i] = As[ty * TM + i][kk];
            float b[TN];
            if (TN == 4) {
                float4 bv = ((const float4*)&Bs[kk][0])[tx];
                b[0] = bv.x; b[1] = bv.y; b[2] = bv.z; b[3] = bv.w;
            } else {
                float2 bv = ((const float2*)&Bs[kk][0])[tx];
                b[0] = bv.x; b[1] = bv.y;
            }
#pragma unroll
            for (int i = 0; i < TM; i++)
#pragma unroll
                for (int j = 0; j < TN; j++) acc[i][j] += a[i] * b[j];
        }
        __syncthreads();
    }

#pragma unroll
    for (int i = 0; i < TM; i++) {
        int gr = row0 + ty * TM + i;
        if (gr < M) {
            if (TN == 4) {
                float4 o = make_float4(acc[i][0], acc[i][1], acc[i][2], acc[i][3]);
                ((float4*)&C[(size_t)gr * N])[tx] = o;
            } else {
                float2 o = make_float2(acc[i][0], acc[i][1]);
                ((float2*)&C[(size_t)gr * N])[tx] = o;
            }
        }
    }
}

// ---------------- layer1 pull-aggregation: warp per node, 128 cols -----------
// hr[v] = relu( dinv[v]*(sum_s dinv[s]*h1[s] + dinv[v]*h1[v]) + b1 )
__global__ void agg128_kernel(const float* __restrict__ h,
                              const float* __restrict__ b1,
                              float* __restrict__ hr) {
    int v = (blockIdx.x * blockDim.x + threadIdx.x) >> 5;
    int lane = threadIdx.x & 31;
    if (v >= N_NODES) return;

    int beg = g_rowstart[v];
    int end = g_rowstart[v + 1];

    float4 acc = make_float4(0.f, 0.f, 0.f, 0.f);
    int e = beg;
    for (; e + 4 <= end; e += 4) {
        int s0 = g_csr_src[e];
        int s1 = g_csr_src[e + 1];
        int s2 = g_csr_src[e + 2];
        int s3 = g_csr_src[e + 3];
        float c0 = g_dinv[s0];
        float c1 = g_dinv[s1];
        float c2 = g_dinv[s2];
        float c3 = g_dinv[s3];
        float4 v0 = ((const float4*)(h + (size_t)s0 * 128))[lane];
        float4 v1 = ((const float4*)(h + (size_t)s1 * 128))[lane];
        float4 v2 = ((const float4*)(h + (size_t)s2 * 128))[lane];
        float4 v3 = ((const float4*)(h + (size_t)s3 * 128))[lane];
        acc.x += v0.x * c0 + v1.x * c1 + v2.x * c2 + v3.x * c3;
        acc.y += v0.y * c0 + v1.y * c1 + v2.y * c2 + v3.y * c3;
        acc.z += v0.z * c0 + v1.z * c1 + v2.z * c2 + v3.z * c3;
        acc.w += v0.w * c0 + v1.w * c1 + v2.w * c2 + v3.w * c3;
    }
    for (; e < end; e++) {
        int s0 = g_csr_src[e];
        float c0 = g_dinv[s0];
        float4 v0 = ((const float4*)(h + (size_t)s0 * 128))[lane];
        acc.x += v0.x * c0;
        acc.y += v0.y * c0;
        acc.z += v0.z * c0;
        acc.w += v0.w * c0;
    }

    float dv = g_dinv[v];
    float4 self = ((const float4*)(h + (size_t)v * 128))[lane];
    float4 bb = ((const float4*)b1)[lane];
    float4 r;
    r.x = fmaxf((acc.x + self.x * dv) * dv + bb.x, 0.f);
    r.y = fmaxf((acc.y + self.y * dv) * dv + bb.y, 0.f);
    r.z = fmaxf((acc.z + self.z * dv) * dv + bb.z, 0.f);
    r.w = fmaxf((acc.w + self.w * dv) * dv + bb.w, 0.f);
    ((float4*)(hr + (size_t)v * 128))[lane] = r;
}

// ---------------- layer2 pull-aggregation + log_softmax: warp per node -------
__global__ void agg64_final_kernel(const float* __restrict__ h,
                                   const float* __restrict__ b2,
                                   float* __restrict__ out) {
    int v = (blockIdx.x * blockDim.x + threadIdx.x) >> 5;
    int lane = threadIdx.x & 31;
    if (v >= N_NODES) return;

    int beg = g_rowstart[v];
    int end = g_rowstart[v + 1];

    float2 acc = make_float2(0.f, 0.f);
    int e = beg;
    for (; e + 4 <= end; e += 4) {
        int s0 = g_csr_src[e];
        int s1 = g_csr_src[e + 1];
        int s2 = g_csr_src[e + 2];
        int s3 = g_csr_src[e + 3];
        float c0 = g_dinv[s0];
        float c1 = g_dinv[s1];
        float c2 = g_dinv[s2];
        float c3 = g_dinv[s3];
        float2 v0 = ((const float2*)(h + (size_t)s0 * 64))[lane];
        float2 v1 = ((const float2*)(h + (size_t)s1 * 64))[lane];
        float2 v2 = ((const float2*)(h + (size_t)s2 * 64))[lane];
        float2 v3 = ((const float2*)(h + (size_t)s3 * 64))[lane];
        acc.x += v0.x * c0 + v1.x * c1 + v2.x * c2 + v3.x * c3;
        acc.y += v0.y * c0 + v1.y * c1 + v2.y * c2 + v3.y * c3;
    }
    for (; e < end; e++) {
        int s0 = g_csr_src[e];
        float c0 = g_dinv[s0];
        float2 v0 = ((const float2*)(h + (size_t)s0 * 64))[lane];
        acc.x += v0.x * c0;
        acc.y += v0.y * c0;
    }

    float dv = g_dinv[v];
    float2 self = ((const float2*)(h + (size_t)v * 64))[lane];
    float2 bb = ((const float2*)b2)[lane];
    float v0 = (acc.x + self.x * dv) * dv + bb.x;
    float v1 = (acc.y + self.y * dv) * dv + bb.y;

    float m = fmaxf(v0, v1);
#pragma unroll
    for (int o = 16; o > 0; o >>= 1)
        m = fmaxf(m, __shfl_xor_sync(0xFFFFFFFF, m, o));
    float s = __expf(v0 - m) + __expf(v1 - m);
#pragma unroll
    for (int o = 16; o > 0; o >>= 1)
        s += __shfl_xor_sync(0xFFFFFFFF, s, o);
    float lse = m + logf(s);
    ((float2*)(out + (size_t)v * 64))[lane] = make_float2(v0 - lse, v1 - lse);
}

// ---------------- launch ------------------------------------------------------
extern "C" void kernel_launch(void* const* d_in, const int* in_sizes, int n_in,
                              void* d_out, int out_size) {
    const float* x = (const float*)d_in[0];
    const int* ei = (const int*)d_in[1];
    const float* W1 = (const float*)d_in[2];
    const float* b1 = (const float*)d_in[3];
    const float* W2 = (const float*)d_in[4];
    const float* b2 = (const float*)d_in[5];
    float* out = (float*)d_out;

    int E = in_sizes[1] / 2;
    const int* src = ei;
    const int* dst = ei + E;

    float* h1; cudaGetSymbolAddress((void**)&h1, g_h1);
    float* hr; cudaGetSymbolAddress((void**)&hr, g_hr);
    float* h2; cudaGetSymbolAddress((void**)&h2, g_h2);

    // graph prep: CSR by destination (no fp atomics anywhere)
    zero_deg_kernel<<<(N_NODES + 255) / 256, 256>>>();
    degree_kernel<<<(E + 255) / 256, 256>>>(dst, E);
    scan_kernel<<<1, 1024>>>();
    dinv_kernel<<<(N_NODES + 255) / 256, 256>>>();
    fill_kernel<<<(E + 255) / 256, 256>>>(src, dst, E);

    // layer 1: transform then pull-aggregate (+bias+relu fused)
    gemm_kernel<HID><<<(N_NODES + 63) / 64, 256>>>(x, W1, h1, N_NODES);
    agg128_kernel<<<(N_NODES * 32 + 255) / 256, 256>>>(h1, b1, hr);

    // layer 2: transform then pull-aggregate (+bias+log_softmax fused)
    gemm_kernel<OUT_DIM><<<(N_NODES + 63) / 64, 256>>>(hr, W2, h2, N_NODES);
    agg64_final_kernel<<<(N_NODES * 32 + 255) / 256, 256>>>(h2, b2, out);
}

// round 7
// speedup vs baseline: 2.0745x; 1.0373x over previous
#include <cuda_runtime.h>
#include <math.h>
#include <stdint.h>

#define N_NODES 100000
#define E_MAX   1600000
#define IN_DIM 128
#define HID 128
#define OUT_DIM 64

// ---------------- scratch (device globals; no allocation allowed) -----------
__device__ float g_h1[(size_t)N_NODES * HID];       // x @ W1
__device__ float g_hr[(size_t)N_NODES * HID];       // relu(aggregated layer1)
__device__ float g_h2[(size_t)N_NODES * OUT_DIM];   // hr @ W2
__device__ float g_dinv[N_NODES];
__device__ int   g_deg[N_NODES];
__device__ int   g_rowstart[N_NODES + 1];
__device__ int   g_cursor[N_NODES];
__device__ int   g_csr_src[E_MAX];

// ---------------- zero degree ------------------------------------------------
__global__ void zero_deg_kernel() {
    int i = blockIdx.x * blockDim.x + threadIdx.x;
    if (i < N_NODES) g_deg[i] = 0;
}

// ---------------- degree ------------------------------------------------------
__global__ void degree_kernel(const int* __restrict__ dst, int E) {
    int i = blockIdx.x * blockDim.x + threadIdx.x;
    if (i < E) atomicAdd(&g_deg[dst[i]], 1);
}

// ---------------- dinv --------------------------------------------------------
__global__ void dinv_kernel() {
    int v = blockIdx.x * blockDim.x + threadIdx.x;
    if (v < N_NODES) {
        float deg = (float)(g_deg[v] + 1);  // +1 self loop -> always > 0
        g_dinv[v] = rsqrtf(deg);
    }
}

// ---------------- single-block exclusive scan of deg -> rowstart, cursor -----
__global__ void scan_kernel() {
    const int T = 1024;
    __shared__ int sh[T];
    int tid = threadIdx.x;
    const int CH = (N_NODES + T - 1) / T;  // 98
    int base = tid * CH;
    int s = 0;
    for (int i = 0; i < CH; i++) {
        int idx = base + i;
        if (idx < N_NODES) s += g_deg[idx];
    }
    sh[tid] = s;
    __syncthreads();
    for (int off = 1; off < T; off <<= 1) {
        int v = (tid >= off) ? sh[tid - off] : 0;
        __syncthreads();
        sh[tid] += v;
        __syncthreads();
    }
    int run = sh[tid] - s;  // exclusive prefix for this chunk
    for (int i = 0; i < CH; i++) {
        int idx = base + i;
        if (idx < N_NODES) {
            g_rowstart[idx] = run;
            g_cursor[idx] = run;
            run += g_deg[idx];
        }
    }
    if (tid == T - 1) g_rowstart[N_NODES] = sh[T - 1];
}

// ---------------- counting-sort fill: group edge srcs by dst ------------------
__global__ void fill_kernel(const int* __restrict__ src,
                            const int* __restrict__ dst, int E) {
    int i = blockIdx.x * blockDim.x + threadIdx.x;
    if (i < E) {
        int d = dst[i];
        int p = atomicAdd(&g_cursor[d], 1);
        g_csr_src[p] = src[i];
    }
}

// ---------------- SGEMM: C[M,N] = A[M,K=128] * B[128,N] ----------------------
template <int N>
__global__ void __launch_bounds__(256) gemm_kernel(
        const float* __restrict__ A,
        const float* __restrict__ B,
        float* __restrict__ C, int M) {
    constexpr int K = 128;
    constexpr int BM = 64;
    constexpr int BK = 32;
    constexpr int TN = N / 32;  // 4 for N=128, 2 for N=64
    constexpr int TM = 8;

    __shared__ float As[BM][BK + 1];
    __shared__ float Bs[BK][N];

    int tid = threadIdx.x;
    int tx = tid & 31;
    int ty = tid >> 5;        // 0..7
    int row0 = blockIdx.x * BM;

    float acc[TM][TN];
#pragma unroll
    for (int i = 0; i < TM; i++)
#pragma unroll
        for (int j = 0; j < TN; j++) acc[i][j] = 0.0f;

    for (int k0 = 0; k0 < K; k0 += BK) {
#pragma unroll
        for (int l = 0; l < 8; l++) {
            int e = tid + l * 256;
            int r = e >> 5, c = e & 31;
            int gr = row0 + r;
            As[r][c] = (gr < M) ? A[(size_t)gr * K + k0 + c] : 0.0f;
        }
#pragma unroll
        for (int l = 0; l < (BK * N) / (256 * 4); l++) {
            int e = tid + l * 256;            // float4 index
            int r = e / (N / 4), c = e % (N / 4);
            ((float4*)&Bs[r][0])[c] = ((const float4*)&B[(size_t)(k0 + r) * N])[c];
        }
        __syncthreads();

#pragma unroll
        for (int kk = 0; kk < BK; kk++) {
            float a[TM];
#pragma unroll
            for (int i = 0; i < TM; i++) a[i] = As[ty * TM + i][kk];
            float b[TN];
            if (TN == 4) {
                float4 bv = ((const float4*)&Bs[kk][0])[tx];
                b[0] = bv.x; b[1] = bv.y; b[2] = bv.z; b[3] = bv.w;
            } else {
                float2 bv = ((const float2*)&Bs[kk][0])[tx];
                b[0] = bv.x; b[1] = bv.y;
            }
#pragma unroll
            for (int i = 0; i < TM; i++)
#pragma unroll
                for (int j = 0; j < TN; j++) acc[i][j] += a[i] * b[j];
        }
        __syncthreads();
    }

#pragma unroll
    for (int i = 0; i < TM; i++) {
        int gr = row0 + ty * TM + i;
        if (gr < M) {
            if (TN == 4) {
                float4 o = make_float4(acc[i][0], acc[i][1], acc[i][2], acc[i][3]);
                ((float4*)&C[(size_t)gr * N])[tx] = o;
            } else {
                float2 o = make_float2(acc[i][0], acc[i][1]);
                ((float2*)&C[(size_t)gr * N])[tx] = o;
            }
        }
    }
}

// ---------------- layer1 pull-aggregation: warp per node, 128 cols -----------
// hr[v] = relu( dinv[v]*(sum_s dinv[s]*h1[s] + dinv[v]*h1[v]) + b1 )
__global__ void agg128_kernel(const float* __restrict__ h,
                              const float* __restrict__ b1,
                              float* __restrict__ hr) {
    int v = (blockIdx.x * blockDim.x + threadIdx.x) >> 5;
    int lane = threadIdx.x & 31;
    if (v >= N_NODES) return;

    int beg = g_rowstart[v];
    int end = g_rowstart[v + 1];

    float4 acc = make_float4(0.f, 0.f, 0.f, 0.f);
    int e = beg;
    // 8 rows in flight
    for (; e + 8 <= end; e += 8) {
        int   sx[8];
        float cx[8];
#pragma unroll
        for (int q = 0; q < 8; q++) sx[q] = g_csr_src[e + q];
#pragma unroll
        for (int q = 0; q < 8; q++) cx[q] = g_dinv[sx[q]];
        float4 vv[8];
#pragma unroll
        for (int q = 0; q < 8; q++)
            vv[q] = ((const float4*)(h + (size_t)sx[q] * 128))[lane];
#pragma unroll
        for (int q = 0; q < 8; q++) {
            acc.x += vv[q].x * cx[q];
            acc.y += vv[q].y * cx[q];
            acc.z += vv[q].z * cx[q];
            acc.w += vv[q].w * cx[q];
        }
    }
    for (; e + 4 <= end; e += 4) {
        int   sx[4];
        float cx[4];
#pragma unroll
        for (int q = 0; q < 4; q++) sx[q] = g_csr_src[e + q];
#pragma unroll
        for (int q = 0; q < 4; q++) cx[q] = g_dinv[sx[q]];
        float4 vv[4];
#pragma unroll
        for (int q = 0; q < 4; q++)
            vv[q] = ((const float4*)(h + (size_t)sx[q] * 128))[lane];
#pragma unroll
        for (int q = 0; q < 4; q++) {
            acc.x += vv[q].x * cx[q];
            acc.y += vv[q].y * cx[q];
            acc.z += vv[q].z * cx[q];
            acc.w += vv[q].w * cx[q];
        }
    }
    for (; e < end; e++) {
        int s0 = g_csr_src[e];
        float c0 = g_dinv[s0];
        float4 v0 = ((const float4*)(h + (size_t)s0 * 128))[lane];
        acc.x += v0.x * c0;
        acc.y += v0.y * c0;
        acc.z += v0.z * c0;
        acc.w += v0.w * c0;
    }

    float dv = g_dinv[v];
    float4 self = ((const float4*)(h + (size_t)v * 128))[lane];
    float4 bb = ((const float4*)b1)[lane];
    float4 r;
    r.x = fmaxf((acc.x + self.x * dv) * dv + bb.x, 0.f);
    r.y = fmaxf((acc.y + self.y * dv) * dv + bb.y, 0.f);
    r.z = fmaxf((acc.z + self.z * dv) * dv + bb.z, 0.f);
    r.w = fmaxf((acc.w + self.w * dv) * dv + bb.w, 0.f);
    ((float4*)(hr + (size_t)v * 128))[lane] = r;
}

// ---------------- layer2 pull-aggregation + log_softmax ----------------------
// half-warp per node: 16 lanes x float4 = 64 floats per row
__global__ void agg64_final_kernel(const float* __restrict__ h,
                                   const float* __restrict__ b2,
                                   float* __restrict__ out) {
    int gw = (blockIdx.x * blockDim.x + threadIdx.x) >> 5;
    int lane = threadIdx.x & 31;
    int half = lane >> 4;
    int sub = lane & 15;
    int v = gw * 2 + half;
    if (v >= N_NODES) return;

    int beg = g_rowstart[v];
    int end = g_rowstart[v + 1];

    float4 acc = make_float4(0.f, 0.f, 0.f, 0.f);
    int e = beg;
    for (; e + 4 <= end; e += 4) {
        int   sx[4];
        float cx[4];
#pragma unroll
        for (int q = 0; q < 4; q++) sx[q] = g_csr_src[e + q];
#pragma unroll
        for (int q = 0; q < 4; q++) cx[q] = g_dinv[sx[q]];
        float4 vv[4];
#pragma unroll
        for (int q = 0; q < 4; q++)
            vv[q] = ((const float4*)(h + (size_t)sx[q] * 64))[sub];
#pragma unroll
        for (int q = 0; q < 4; q++) {
            acc.x += vv[q].x * cx[q];
            acc.y += vv[q].y * cx[q];
            acc.z += vv[q].z * cx[q];
            acc.w += vv[q].w * cx[q];
        }
    }
    for (; e < end; e++) {
        int s0 = g_csr_src[e];
        float c0 = g_dinv[s0];
        float4 v0 = ((const float4*)(h + (size_t)s0 * 64))[sub];
        acc.x += v0.x * c0;
        acc.y += v0.y * c0;
        acc.z += v0.z * c0;
        acc.w += v0.w * c0;
    }

    float dv = g_dinv[v];
    float4 self = ((const float4*)(h + (size_t)v * 64))[sub];
    float4 bb = ((const float4*)b2)[sub];
    float t0 = (acc.x + self.x * dv) * dv + bb.x;
    float t1 = (acc.y + self.y * dv) * dv + bb.y;
    float t2 = (acc.z + self.z * dv) * dv + bb.z;
    float t3 = (acc.w + self.w * dv) * dv + bb.w;

    float m = fmaxf(fmaxf(t0, t1), fmaxf(t2, t3));
#pragma unroll
    for (int o = 8; o > 0; o >>= 1)
        m = fmaxf(m, __shfl_xor_sync(0xFFFFFFFF, m, o));
    float s = __expf(t0 - m) + __expf(t1 - m) + __expf(t2 - m) + __expf(t3 - m);
#pragma unroll
    for (int o = 8; o > 0; o >>= 1)
        s += __shfl_xor_sync(0xFFFFFFFF, s, o);
    float lse = m + logf(s);
    float4 r = make_float4(t0 - lse, t1 - lse, t2 - lse, t3 - lse);
    ((float4*)(out + (size_t)v * 64))[sub] = r;
}

// ---------------- host-side stream/event handles (host objects only) ---------
struct HostRes {
    cudaStream_t s2;
    cudaEvent_t ev_fork, ev_join;
    HostRes() {
        cudaStreamCreateWithFlags(&s2, cudaStreamNonBlocking);
        cudaEventCreateWithFlags(&ev_fork, cudaEventDisableTiming);
        cudaEventCreateWithFlags(&ev_join, cudaEventDisableTiming);
    }
};

// ---------------- launch ------------------------------------------------------
extern "C" void kernel_launch(void* const* d_in, const int* in_sizes, int n_in,
                              void* d_out, int out_size) {
    const float* x = (const float*)d_in[0];
    const int* ei = (const int*)d_in[1];
    const float* W1 = (const float*)d_in[2];
    const float* b1 = (const float*)d_in[3];
    const float* W2 = (const float*)d_in[4];
    const float* b2 = (const float*)d_in[5];
    float* out = (float*)d_out;

    int E = in_sizes[1] / 2;
    const int* src = ei;
    const int* dst = ei + E;

    float* h1; cudaGetSymbolAddress((void**)&h1, g_h1);
    float* hr; cudaGetSymbolAddress((void**)&hr, g_hr);
    float* h2; cudaGetSymbolAddress((void**)&h2, g_h2);

    static HostRes R;  // host handles only; device work identical every call

    // fork: GEMM1 (depends only on x,W1) runs on R.s2 concurrently with CSR prep
    cudaEventRecord(R.ev_fork, 0);
    cudaStreamWaitEvent(R.s2, R.ev_fork, 0);
    gemm_kernel<HID><<<(N_NODES + 63) / 64, 256, 0, R.s2>>>(x, W1, h1, N_NODES);
    cudaEventRecord(R.ev_join, R.s2);

    // CSR prep on the capture stream (no fp atomics anywhere)
    zero_deg_kernel<<<(N_NODES + 255) / 256, 256>>>();
    degree_kernel<<<(E + 255) / 256, 256>>>(dst, E);
    scan_kernel<<<1, 1024>>>();
    dinv_kernel<<<(N_NODES + 255) / 256, 256>>>();
    fill_kernel<<<(E + 255) / 256, 256>>>(src, dst, E);

    // join before aggregation needs h1
    cudaStreamWaitEvent(0, R.ev_join, 0);

    // layer 1 aggregate (+bias+relu fused)
    agg128_kernel<<<(N_NODES * 32 + 255) / 256, 256>>>(h1, b1, hr);

    // layer 2: transform then aggregate (+bias+log_softmax fused)
    gemm_kernel<OUT_DIM><<<(N_NODES + 63) / 64, 256>>>(hr, W2, h2, N_NODES);
    {
        long long warps = (N_NODES + 1) / 2;
        long long threads = warps * 32;
        int blocks = (int)((threads + 255) / 256);
        agg64_final_kernel<<<blocks, 256>>>(h2, b2, out);
    }
}

// round 8
// speedup vs baseline: 3.2417x; 1.5627x over previous
#include <cuda_runtime.h>
#include <math.h>
#include <stdint.h>

#define N_NODES 100000
#define E_MAX   1600000
#define IN_DIM 128
#define HID 128
#define OUT_DIM 64
#define NB ((N_NODES + 255) / 256)

// ---------------- scratch (device globals; no allocation allowed) -----------
__device__ float g_h1[(size_t)N_NODES * HID];       // x @ W1
__device__ float g_hr[(size_t)N_NODES * HID];       // relu(aggregated layer1)
__device__ float g_h2[(size_t)N_NODES * OUT_DIM];   // hr @ W2
__device__ float g_dinv[N_NODES];
__device__ int   g_deg[N_NODES];
__device__ int   g_rowstart[N_NODES + 1];
__device__ int   g_cursor[N_NODES];
__device__ int   g_csr_src[E_MAX];
__device__ int   g_blocksum[NB];
__device__ int   g_blockoff[NB];

// ---------------- zero degree ------------------------------------------------
__global__ void zero_deg_kernel() {
    int i = blockIdx.x * blockDim.x + threadIdx.x;
    if (i < N_NODES) g_deg[i] = 0;
}

// ---------------- degree ------------------------------------------------------
__global__ void degree_kernel(const int* __restrict__ dst, int E) {
    int i = blockIdx.x * blockDim.x + threadIdx.x;
    if (i < E) atomicAdd(&g_deg[dst[i]], 1);
}

// ---------------- dinv --------------------------------------------------------
__global__ void dinv_kernel() {
    int v = blockIdx.x * blockDim.x + threadIdx.x;
    if (v < N_NODES) {
        float deg = (float)(g_deg[v] + 1);  // +1 self loop -> always > 0
        g_dinv[v] = rsqrtf(deg);
    }
}

// ---------------- 3-phase parallel exclusive scan of deg ---------------------
// Phase A: per-block sums (coalesced)
__global__ void scanA_kernel() {
    __shared__ int sh[256];
    int t = threadIdx.x;
    int idx = blockIdx.x * 256 + t;
    int d = (idx < N_NODES) ? g_deg[idx] : 0;
    sh[t] = d;
    __syncthreads();
#pragma unroll
    for (int off = 128; off > 0; off >>= 1) {
        if (t < off) sh[t] += sh[t + off];
        __syncthreads();
    }
    if (t == 0) g_blocksum[blockIdx.x] = sh[0];
}

// Phase B: single small block scans the NB partials
__global__ void scanB_kernel() {
    __shared__ int sh[512];
    int t = threadIdx.x;
    int v = (t < NB) ? g_blocksum[t] : 0;
    sh[t] = v;
    __syncthreads();
    for (int off = 1; off < 512; off <<= 1) {
        int u = (t >= off) ? sh[t - off] : 0;
        __syncthreads();
        sh[t] += u;
        __syncthreads();
    }
    if (t < NB) g_blockoff[t] = sh[t] - v;  // exclusive block offset
    if (t == 511) g_rowstart[N_NODES] = sh[511];
}

// Phase C: per-block exclusive scan + offset -> rowstart, cursor
__global__ void scanC_kernel() {
    __shared__ int sh[256];
    int t = threadIdx.x;
    int idx = blockIdx.x * 256 + t;
    int d = (idx < N_NODES) ? g_deg[idx] : 0;
    sh[t] = d;
    __syncthreads();
    for (int off = 1; off < 256; off <<= 1) {
        int u = (t >= off) ? sh[t - off] : 0;
        __syncthreads();
        sh[t] += u;
        __syncthreads();
    }
    if (idx < N_NODES) {
        int excl = g_blockoff[blockIdx.x] + sh[t] - d;
        g_rowstart[idx] = excl;
        g_cursor[idx] = excl;
    }
}

// ---------------- counting-sort fill: group edge srcs by dst ------------------
__global__ void fill_kernel(const int* __restrict__ src,
                            const int* __restrict__ dst, int E) {
    int i = blockIdx.x * blockDim.x + threadIdx.x;
    if (i < E) {
        int d = dst[i];
        int p = atomicAdd(&g_cursor[d], 1);
        g_csr_src[p] = src[i];
    }
}

// ---------------- SGEMM: C[M,N] = A[M,K=128] * B[128,N] ----------------------
template <int N>
__global__ void __launch_bounds__(256) gemm_kernel(
        const float* __restrict__ A,
        const float* __restrict__ B,
        float* __restrict__ C, int M) {
    constexpr int K = 128;
    constexpr int BM = 64;
    constexpr int BK = 32;
    constexpr int TN = N / 32;  // 4 for N=128, 2 for N=64
    constexpr int TM = 8;

    __shared__ float As[BM][BK + 1];
    __shared__ float Bs[BK][N];

    int tid = threadIdx.x;
    int tx = tid & 31;
    int ty = tid >> 5;        // 0..7
    int row0 = blockIdx.x * BM;

    float acc[TM][TN];
#pragma unroll
    for (int i = 0; i < TM; i++)
#pragma unroll
        for (int j = 0; j < TN; j++) acc[i][j] = 0.0f;

    for (int k0 = 0; k0 < K; k0 += BK) {
#pragma unroll
        for (int l = 0; l < 8; l++) {
            int e = tid + l * 256;
            int r = e >> 5, c = e & 31;
            int gr = row0 + r;
            As[r][c] = (gr < M) ? A[(size_t)gr * K + k0 + c] : 0.0f;
        }
#pragma unroll
        for (int l = 0; l < (BK * N) / (256 * 4); l++) {
            int e = tid + l * 256;            // float4 index
            int r = e / (N / 4), c = e % (N / 4);
            ((float4*)&Bs[r][0])[c] = ((const float4*)&B[(size_t)(k0 + r) * N])[c];
        }
        __syncthreads();

#pragma unroll
        for (int kk = 0; kk < BK; kk++) {
            float a[TM];
#pragma unroll
            for (int i = 0; i < TM; i++) a[i] = As[ty * TM + i][kk];
            float b[TN];
            if (TN == 4) {
                float4 bv = ((const float4*)&Bs[kk][0])[tx];
                b[0] = bv.x; b[1] = bv.y; b[2] = bv.z; b[3] = bv.w;
            } else {
                float2 bv = ((const float2*)&Bs[kk][0])[tx];
                b[0] = bv.x; b[1] = bv.y;
            }
#pragma unroll
            for (int i = 0; i < TM; i++)
#pragma unroll
                for (int j = 0; j < TN; j++) acc[i][j] += a[i] * b[j];
        }
        __syncthreads();
    }

#pragma unroll
    for (int i = 0; i < TM; i++) {
        int gr = row0 + ty * TM + i;
        if (gr < M) {
            if (TN == 4) {
                float4 o = make_float4(acc[i][0], acc[i][1], acc[i][2], acc[i][3]);
                ((float4*)&C[(size_t)gr * N])[tx] = o;
            } else {
                float2 o = make_float2(acc[i][0], acc[i][1]);
                ((float2*)&C[(size_t)gr * N])[tx] = o;
            }
        }
    }
}

// ---------------- layer1 pull-aggregation: warp per node, 128 cols -----------
// hr[v] = relu( dinv[v]*(sum_s dinv[s]*h1[s] + dinv[v]*h1[v]) + b1 )
__global__ void agg128_kernel(const float* __restrict__ h,
                              const float* __restrict__ b1,
                              float* __restrict__ hr) {
    int v = (blockIdx.x * blockDim.x + threadIdx.x) >> 5;
    int lane = threadIdx.x & 31;
    if (v >= N_NODES) return;

    int beg = g_rowstart[v];
    int end = g_rowstart[v + 1];

    float4 acc = make_float4(0.f, 0.f, 0.f, 0.f);
    int e = beg;
    // 8 rows in flight
    for (; e + 8 <= end; e += 8) {
        int   sx[8];
        float cx[8];
#pragma unroll
        for (int q = 0; q < 8; q++) sx[q] = g_csr_src[e + q];
#pragma unroll
        for (int q = 0; q < 8; q++) cx[q] = g_dinv[sx[q]];
        float4 vv[8];
#pragma unroll
        for (int q = 0; q < 8; q++)
            vv[q] = ((const float4*)(h + (size_t)sx[q] * 128))[lane];
#pragma unroll
        for (int q = 0; q < 8; q++) {
            acc.x += vv[q].x * cx[q];
            acc.y += vv[q].y * cx[q];
            acc.z += vv[q].z * cx[q];
            acc.w += vv[q].w * cx[q];
        }
    }
    for (; e + 4 <= end; e += 4) {
        int   sx[4];
        float cx[4];
#pragma unroll
        for (int q = 0; q < 4; q++) sx[q] = g_csr_src[e + q];
#pragma unroll
        for (int q = 0; q < 4; q++) cx[q] = g_dinv[sx[q]];
        float4 vv[4];
#pragma unroll
        for (int q = 0; q < 4; q++)
            vv[q] = ((const float4*)(h + (size_t)sx[q] * 128))[lane];
#pragma unroll
        for (int q = 0; q < 4; q++) {
            acc.x += vv[q].x * cx[q];
            acc.y += vv[q].y * cx[q];
            acc.z += vv[q].z * cx[q];
            acc.w += vv[q].w * cx[q];
        }
    }
    for (; e < end; e++) {
        int s0 = g_csr_src[e];
        float c0 = g_dinv[s0];
        float4 v0 = ((const float4*)(h + (size_t)s0 * 128))[lane];
        acc.x += v0.x * c0;
        acc.y += v0.y * c0;
        acc.z += v0.z * c0;
        acc.w += v0.w * c0;
    }

    float dv = g_dinv[v];
    float4 self = ((const float4*)(h + (size_t)v * 128))[lane];
    float4 bb = ((const float4*)b1)[lane];
    float4 r;
    r.x = fmaxf((acc.x + self.x * dv) * dv + bb.x, 0.f);
    r.y = fmaxf((acc.y + self.y * dv) * dv + bb.y, 0.f);
    r.z = fmaxf((acc.z + self.z * dv) * dv + bb.z, 0.f);
    r.w = fmaxf((acc.w + self.w * dv) * dv + bb.w, 0.f);
    ((float4*)(hr + (size_t)v * 128))[lane] = r;
}

// ---------------- layer2 pull-aggregation + log_softmax ----------------------
// half-warp per node: 16 lanes x float4 = 64 floats per row
__global__ void agg64_final_kernel(const float* __restrict__ h,
                                   const float* __restrict__ b2,
                                   float* __restrict__ out) {
    int gw = (blockIdx.x * blockDim.x + threadIdx.x) >> 5;
    int lane = threadIdx.x & 31;
    int half = lane >> 4;
    int sub = lane & 15;
    int v = gw * 2 + half;
    if (v >= N_NODES) return;

    int beg = g_rowstart[v];
    int end = g_rowstart[v + 1];

    float4 acc = make_float4(0.f, 0.f, 0.f, 0.f);
    int e = beg;
    for (; e + 4 <= end; e += 4) {
        int   sx[4];
        float cx[4];
#pragma unroll
        for (int q = 0; q < 4; q++) sx[q] = g_csr_src[e + q];
#pragma unroll
        for (int q = 0; q < 4; q++) cx[q] = g_dinv[sx[q]];
        float4 vv[4];
#pragma unroll
        for (int q = 0; q < 4; q++)
            vv[q] = ((const float4*)(h + (size_t)sx[q] * 64))[sub];
#pragma unroll
        for (int q = 0; q < 4; q++) {
            acc.x += vv[q].x * cx[q];
            acc.y += vv[q].y * cx[q];
            acc.z += vv[q].z * cx[q];
            acc.w += vv[q].w * cx[q];
        }
    }
    for (; e < end; e++) {
        int s0 = g_csr_src[e];
        float c0 = g_dinv[s0];
        float4 v0 = ((const float4*)(h + (size_t)s0 * 64))[sub];
        acc.x += v0.x * c0;
        acc.y += v0.y * c0;
        acc.z += v0.z * c0;
        acc.w += v0.w * c0;
    }

    float dv = g_dinv[v];
    float4 self = ((const float4*)(h + (size_t)v * 64))[sub];
    float4 bb = ((const float4*)b2)[sub];
    float t0 = (acc.x + self.x * dv) * dv + bb.x;
    float t1 = (acc.y + self.y * dv) * dv + bb.y;
    float t2 = (acc.z + self.z * dv) * dv + bb.z;
    float t3 = (acc.w + self.w * dv) * dv + bb.w;

    float m = fmaxf(fmaxf(t0, t1), fmaxf(t2, t3));
#pragma unroll
    for (int o = 8; o > 0; o >>= 1)
        m = fmaxf(m, __shfl_xor_sync(0xFFFFFFFF, m, o));
    float s = __expf(t0 - m) + __expf(t1 - m) + __expf(t2 - m) + __expf(t3 - m);
#pragma unroll
    for (int o = 8; o > 0; o >>= 1)
        s += __shfl_xor_sync(0xFFFFFFFF, s, o);
    float lse = m + logf(s);
    float4 r = make_float4(t0 - lse, t1 - lse, t2 - lse, t3 - lse);
    ((float4*)(out + (size_t)v * 64))[sub] = r;
}

// ---------------- host-side stream/event handles (host objects only) ---------
struct HostRes {
    cudaStream_t s2;
    cudaEvent_t ev_fork, ev_join;
    HostRes() {
        cudaStreamCreateWithFlags(&s2, cudaStreamNonBlocking);
        cudaEventCreateWithFlags(&ev_fork, cudaEventDisableTiming);
        cudaEventCreateWithFlags(&ev_join, cudaEventDisableTiming);
    }
};

// ---------------- launch ------------------------------------------------------
extern "C" void kernel_launch(void* const* d_in, const int* in_sizes, int n_in,
                              void* d_out, int out_size) {
    const float* x = (const float*)d_in[0];
    const int* ei = (const int*)d_in[1];
    const float* W1 = (const float*)d_in[2];
    const float* b1 = (const float*)d_in[3];
    const float* W2 = (const float*)d_in[4];
    const float* b2 = (const float*)d_in[5];
    float* out = (float*)d_out;

    int E = in_sizes[1] / 2;
    const int* src = ei;
    const int* dst = ei + E;

    float* h1; cudaGetSymbolAddress((void**)&h1, g_h1);
    float* hr; cudaGetSymbolAddress((void**)&hr, g_hr);
    float* h2; cudaGetSymbolAddress((void**)&h2, g_h2);

    static HostRes R;  // host handles only; device work identical every call

    // fork: GEMM1 (depends only on x,W1) runs on R.s2 concurrently with CSR prep
    cudaEventRecord(R.ev_fork, 0);
    cudaStreamWaitEvent(R.s2, R.ev_fork, 0);
    gemm_kernel<HID><<<(N_NODES + 63) / 64, 256, 0, R.s2>>>(x, W1, h1, N_NODES);
    cudaEventRecord(R.ev_join, R.s2);

    // CSR prep on the capture stream (no fp atomics anywhere)
    zero_deg_kernel<<<(N_NODES + 255) / 256, 256>>>();
    degree_kernel<<<(E + 255) / 256, 256>>>(dst, E);
    scanA_kernel<<<NB, 256>>>();
    scanB_kernel<<<1, 512>>>();
    scanC_kernel<<<NB, 256>>>();
    dinv_kernel<<<(N_NODES + 255) / 256, 256>>>();
    fill_kernel<<<(E + 255) / 256, 256>>>(src, dst, E);

    // join before aggregation needs h1
    cudaStreamWaitEvent(0, R.ev_join, 0);

    // layer 1 aggregate (+bias+relu fused)
    agg128_kernel<<<(N_NODES * 32 + 255) / 256, 256>>>(h1, b1, hr);

    // layer 2: transform then aggregate (+bias+log_softmax fused)
    gemm_kernel<OUT_DIM><<<(N_NODES + 63) / 64, 256>>>(hr, W2, h2, N_NODES);
    {
        long long warps = (N_NODES + 1) / 2;
        long long threads = warps * 32;
        int blocks = (int)((threads + 255) / 256);
        agg64_final_kernel<<<blocks, 256>>>(h2, b2, out);
    }
}

// round 9
// speedup vs baseline: 3.4884x; 1.0761x over previous
#include <cuda_runtime.h>
#include <cuda_fp16.h>
#include <math.h>
#include <stdint.h>

#define N_NODES 100000
#define E_MAX   1600000
#define IN_DIM 128
#define HID 128
#define OUT_DIM 64
#define NB ((N_NODES + 255) / 256)

// ---------------- scratch (device globals; no allocation allowed) -----------
__device__ __half g_h1[(size_t)N_NODES * HID];      // x @ W1  (fp16 storage)
__device__ float  g_hr[(size_t)N_NODES * HID];      // relu(aggregated layer1), fp32
__device__ __half g_h2[(size_t)N_NODES * OUT_DIM];  // hr @ W2 (fp16 storage)
__device__ float  g_dinv[N_NODES];
__device__ int    g_deg[N_NODES];
__device__ int    g_rowstart[N_NODES + 1];
__device__ int    g_cursor[N_NODES];
__device__ int    g_csr_src[E_MAX];
__device__ int    g_blocksum[NB];
__device__ int    g_blockoff[NB];

// ---------------- zero degree ------------------------------------------------
__global__ void zero_deg_kernel() {
    int i = blockIdx.x * blockDim.x + threadIdx.x;
    if (i < N_NODES) g_deg[i] = 0;
}

// ---------------- degree ------------------------------------------------------
__global__ void degree_kernel(const int* __restrict__ dst, int E) {
    int i = blockIdx.x * blockDim.x + threadIdx.x;
    if (i < E) atomicAdd(&g_deg[dst[i]], 1);
}

// ---------------- dinv --------------------------------------------------------
__global__ void dinv_kernel() {
    int v = blockIdx.x * blockDim.x + threadIdx.x;
    if (v < N_NODES) {
        float deg = (float)(g_deg[v] + 1);  // +1 self loop -> always > 0
        g_dinv[v] = rsqrtf(deg);
    }
}

// ---------------- 3-phase parallel exclusive scan of deg ---------------------
__global__ void scanA_kernel() {
    __shared__ int sh[256];
    int t = threadIdx.x;
    int idx = blockIdx.x * 256 + t;
    int d = (idx < N_NODES) ? g_deg[idx] : 0;
    sh[t] = d;
    __syncthreads();
#pragma unroll
    for (int off = 128; off > 0; off >>= 1) {
        if (t < off) sh[t] += sh[t + off];
        __syncthreads();
    }
    if (t == 0) g_blocksum[blockIdx.x] = sh[0];
}

__global__ void scanB_kernel() {
    __shared__ int sh[512];
    int t = threadIdx.x;
    int v = (t < NB) ? g_blocksum[t] : 0;
    sh[t] = v;
    __syncthreads();
    for (int off = 1; off < 512; off <<= 1) {
        int u = (t >= off) ? sh[t - off] : 0;
        __syncthreads();
        sh[t] += u;
        __syncthreads();
    }
    if (t < NB) g_blockoff[t] = sh[t] - v;  // exclusive block offset
    if (t == 511) g_rowstart[N_NODES] = sh[511];
}

__global__ void scanC_kernel() {
    __shared__ int sh[256];
    int t = threadIdx.x;
    int idx = blockIdx.x * 256 + t;
    int d = (idx < N_NODES) ? g_deg[idx] : 0;
    sh[t] = d;
    __syncthreads();
    for (int off = 1; off < 256; off <<= 1) {
        int u = (t >= off) ? sh[t - off] : 0;
        __syncthreads();
        sh[t] += u;
        __syncthreads();
    }
    if (idx < N_NODES) {
        int excl = g_blockoff[blockIdx.x] + sh[t] - d;
        g_rowstart[idx] = excl;
        g_cursor[idx] = excl;
    }
}

// ---------------- counting-sort fill: group edge srcs by dst ------------------
__global__ void fill_kernel(const int* __restrict__ src,
                            const int* __restrict__ dst, int E) {
    int i = blockIdx.x * blockDim.x + threadIdx.x;
    if (i < E) {
        int d = dst[i];
        int p = atomicAdd(&g_cursor[d], 1);
        g_csr_src[p] = src[i];
    }
}

// ---------------- SGEMM: C[M,N](fp16) = A[M,K=128](fp32) * B[128,N](fp32) ----
template <int N>
__global__ void __launch_bounds__(256) gemm_f16_kernel(
        const float* __restrict__ A,
        const float* __restrict__ B,
        __half* __restrict__ C, int M) {
    constexpr int K = 128;
    constexpr int BM = 64;
    constexpr int BK = 32;
    constexpr int TN = N / 32;  // 4 for N=128, 2 for N=64
    constexpr int TM = 8;

    __shared__ float As[BM][BK + 1];
    __shared__ float Bs[BK][N];

    int tid = threadIdx.x;
    int tx = tid & 31;
    int ty = tid >> 5;        // 0..7
    int row0 = blockIdx.x * BM;

    float acc[TM][TN];
#pragma unroll
    for (int i = 0; i < TM; i++)
#pragma unroll
        for (int j = 0; j < TN; j++) acc[i][j] = 0.0f;

    for (int k0 = 0; k0 < K; k0 += BK) {
#pragma unroll
        for (int l = 0; l < 8; l++) {
            int e = tid + l * 256;
            int r = e >> 5, c = e & 31;
            int gr = row0 + r;
            As[r][c] = (gr < M) ? A[(size_t)gr * K + k0 + c] : 0.0f;
        }
#pragma unroll
        for (int l = 0; l < (BK * N) / (256 * 4); l++) {
            int e = tid + l * 256;            // float4 index
            int r = e / (N / 4), c = e % (N / 4);
            ((float4*)&Bs[r][0])[c] = ((const float4*)&B[(size_t)(k0 + r) * N])[c];
        }
        __syncthreads();

#pragma unroll
        for (int kk = 0; kk < BK; kk++) {
            float a[TM];
#pragma unroll
            for (int i = 0; i < TM; i++) a[i] = As[ty * TM + i][kk];
            float b[TN];
            if (TN == 4) {
                float4 bv = ((const float4*)&Bs[kk][0])[tx];
                b[0] = bv.x; b[1] = bv.y; b[2] = bv.z; b[3] = bv.w;
            } else {
                float2 bv = ((const float2*)&Bs[kk][0])[tx];
                b[0] = bv.x; b[1] = bv.y;
            }
#pragma unroll
            for (int i = 0; i < TM; i++)
#pragma unroll
                for (int j = 0; j < TN; j++) acc[i][j] += a[i] * b[j];
        }
        __syncthreads();
    }

#pragma unroll
    for (int i = 0; i < TM; i++) {
        int gr = row0 + ty * TM + i;
        if (gr < M) {
            if (TN == 4) {
                __half2 p0 = __floats2half2_rn(acc[i][0], acc[i][1]);
                __half2 p1 = __floats2half2_rn(acc[i][2], acc[i][3]);
                uint2 o;
                o.x = *(unsigned int*)&p0;
                o.y = *(unsigned int*)&p1;
                ((uint2*)(C + (size_t)gr * N))[tx] = o;
            } else {
                __half2 p0 = __floats2half2_rn(acc[i][0], acc[i][1]);
                ((__half2*)(C + (size_t)gr * N))[tx] = p0;
            }
        }
    }
}

// helper: accumulate fp16x4 (as uint2) * c into float4
__device__ __forceinline__ void acc_f16x4(float4& acc, uint2 v, float c) {
    __half2 a = *(__half2*)&v.x;
    __half2 b = *(__half2*)&v.y;
    float2 f0 = __half22float2(a);
    float2 f1 = __half22float2(b);
    acc.x += f0.x * c;
    acc.y += f0.y * c;
    acc.z += f1.x * c;
    acc.w += f1.y * c;
}

// ---------------- layer1 pull-aggregation: warp per node, 128 fp16 cols ------
// hr[v] = relu( dinv[v]*(sum_s dinv[s]*h1[s] + dinv[v]*h1[v]) + b1 )
__global__ void agg128_kernel(const __half* __restrict__ h,
                              const float* __restrict__ b1,
                              float* __restrict__ hr) {
    int v = (blockIdx.x * blockDim.x + threadIdx.x) >> 5;
    int lane = threadIdx.x & 31;
    if (v >= N_NODES) return;

    int beg = g_rowstart[v];
    int end = g_rowstart[v + 1];

    float4 acc = make_float4(0.f, 0.f, 0.f, 0.f);
    int e = beg;
    for (; e + 8 <= end; e += 8) {
        int   sx[8];
        float cx[8];
#pragma unroll
        for (int q = 0; q < 8; q++) sx[q] = g_csr_src[e + q];
#pragma unroll
        for (int q = 0; q < 8; q++) cx[q] = g_dinv[sx[q]];
        uint2 vv[8];
#pragma unroll
        for (int q = 0; q < 8; q++)
            vv[q] = ((const uint2*)(h + (size_t)sx[q] * 128))[lane];
#pragma unroll
        for (int q = 0; q < 8; q++) acc_f16x4(acc, vv[q], cx[q]);
    }
    for (; e + 4 <= end; e += 4) {
        int   sx[4];
        float cx[4];
#pragma unroll
        for (int q = 0; q < 4; q++) sx[q] = g_csr_src[e + q];
#pragma unroll
        for (int q = 0; q < 4; q++) cx[q] = g_dinv[sx[q]];
        uint2 vv[4];
#pragma unroll
        for (int q = 0; q < 4; q++)
            vv[q] = ((const uint2*)(h + (size_t)sx[q] * 128))[lane];
#pragma unroll
        for (int q = 0; q < 4; q++) acc_f16x4(acc, vv[q], cx[q]);
    }
    for (; e < end; e++) {
        int s0 = g_csr_src[e];
        float c0 = g_dinv[s0];
        uint2 v0 = ((const uint2*)(h + (size_t)s0 * 128))[lane];
        acc_f16x4(acc, v0, c0);
    }

    float dv = g_dinv[v];
    uint2 sv = ((const uint2*)(h + (size_t)v * 128))[lane];
    acc_f16x4(acc, sv, dv);  // self-loop term: dinv[v]*h[v]
    float4 bb = ((const float4*)b1)[lane];
    float4 r;
    r.x = fmaxf(acc.x * dv + bb.x, 0.f);
    r.y = fmaxf(acc.y * dv + bb.y, 0.f);
    r.z = fmaxf(acc.z * dv + bb.z, 0.f);
    r.w = fmaxf(acc.w * dv + bb.w, 0.f);
    ((float4*)(hr + (size_t)v * 128))[lane] = r;
}

// ---------------- layer2 pull-aggregation + log_softmax ----------------------
// half-warp per node: 16 lanes x uint2 = 64 fp16 per row
__global__ void agg64_final_kernel(const __half* __restrict__ h,
                                   const float* __restrict__ b2,
                                   float* __restrict__ out) {
    int gw = (blockIdx.x * blockDim.x + threadIdx.x) >> 5;
    int lane = threadIdx.x & 31;
    int half_id = lane >> 4;
    int sub = lane & 15;
    int v = gw * 2 + half_id;
    if (v >= N_NODES) return;

    int beg = g_rowstart[v];
    int end = g_rowstart[v + 1];

    float4 acc = make_float4(0.f, 0.f, 0.f, 0.f);
    int e = beg;
    for (; e + 4 <= end; e += 4) {
        int   sx[4];
        float cx[4];
#pragma unroll
        for (int q = 0; q < 4; q++) sx[q] = g_csr_src[e + q];
#pragma unroll
        for (int q = 0; q < 4; q++) cx[q] = g_dinv[sx[q]];
        uint2 vv[4];
#pragma unroll
        for (int q = 0; q < 4; q++)
            vv[q] = ((const uint2*)(h + (size_t)sx[q] * 64))[sub];
#pragma unroll
        for (int q = 0; q < 4; q++) acc_f16x4(acc, vv[q], cx[q]);
    }
    for (; e < end; e++) {
        int s0 = g_csr_src[e];
        float c0 = g_dinv[s0];
        uint2 v0 = ((const uint2*)(h + (size_t)s0 * 64))[sub];
        acc_f16x4(acc, v0, c0);
    }

    float dv = g_dinv[v];
    uint2 sv = ((const uint2*)(h + (size_t)v * 64))[sub];
    acc_f16x4(acc, sv, dv);
    float4 bb = ((const float4*)b2)[sub];
    float t0 = acc.x * dv + bb.x;
    float t1 = acc.y * dv + bb.y;
    float t2 = acc.z * dv + bb.z;
    float t3 = acc.w * dv + bb.w;

    float m = fmaxf(fmaxf(t0, t1), fmaxf(t2, t3));
#pragma unroll
    for (int o = 8; o > 0; o >>= 1)
        m = fmaxf(m, __shfl_xor_sync(0xFFFFFFFF, m, o));
    float s = __expf(t0 - m) + __expf(t1 - m) + __expf(t2 - m) + __expf(t3 - m);
#pragma unroll
    for (int o = 8; o > 0; o >>= 1)
        s += __shfl_xor_sync(0xFFFFFFFF, s, o);
    float lse = m + logf(s);
    float4 r = make_float4(t0 - lse, t1 - lse, t2 - lse, t3 - lse);
    ((float4*)(out + (size_t)v * 64))[sub] = r;
}

// ---------------- host-side stream/event handles (host objects only) ---------
struct HostRes {
    cudaStream_t s2;
    cudaEvent_t ev_fork, ev_join;
    HostRes() {
        cudaStreamCreateWithFlags(&s2, cudaStreamNonBlocking);
        cudaEventCreateWithFlags(&ev_fork, cudaEventDisableTiming);
        cudaEventCreateWithFlags(&ev_join, cudaEventDisableTiming);
    }
};

// ---------------- launch ------------------------------------------------------
extern "C" void kernel_launch(void* const* d_in, const int* in_sizes, int n_in,
                              void* d_out, int out_size) {
    const float* x = (const float*)d_in[0];
    const int* ei = (const int*)d_in[1];
    const float* W1 = (const float*)d_in[2];
    const float* b1 = (const float*)d_in[3];
    const float* W2 = (const float*)d_in[4];
    const float* b2 = (const float*)d_in[5];
    float* out = (float*)d_out;

    int E = in_sizes[1] / 2;
    const int* src = ei;
    const int* dst = ei + E;

    __half* h1; cudaGetSymbolAddress((void**)&h1, g_h1);
    float*  hr; cudaGetSymbolAddress((void**)&hr, g_hr);
    __half* h2; cudaGetSymbolAddress((void**)&h2, g_h2);

    static HostRes R;  // host handles only; device work identical every call

    // fork: GEMM1 (depends only on x,W1) runs on R.s2 concurrently with CSR prep
    cudaEventRecord(R.ev_fork, 0);
    cudaStreamWaitEvent(R.s2, R.ev_fork, 0);
    gemm_f16_kernel<HID><<<(N_NODES + 63) / 64, 256, 0, R.s2>>>(x, W1, h1, N_NODES);
    cudaEventRecord(R.ev_join, R.s2);

    // CSR prep on the capture stream (no fp atomics anywhere)
    zero_deg_kernel<<<(N_NODES + 255) / 256, 256>>>();
    degree_kernel<<<(E + 255) / 256, 256>>>(dst, E);
    scanA_kernel<<<NB, 256>>>();
    scanB_kernel<<<1, 512>>>();
    scanC_kernel<<<NB, 256>>>();
    dinv_kernel<<<(N_NODES + 255) / 256, 256>>>();
    fill_kernel<<<(E + 255) / 256, 256>>>(src, dst, E);

    // join before aggregation needs h1
    cudaStreamWaitEvent(0, R.ev_join, 0);

    // layer 1 aggregate (+bias+relu fused)
    agg128_kernel<<<(N_NODES * 32 + 255) / 256, 256>>>(h1, b1, hr);

    // layer 2: transform then aggregate (+bias+log_softmax fused)
    gemm_f16_kernel<OUT_DIM><<<(N_NODES + 63) / 64, 256>>>(hr, W2, h2, N_NODES);
    {
        long long warps = (N_NODES + 1) / 2;
        long long threads = warps * 32;
        int blocks = (int)((threads + 255) / 256);
        agg64_final_kernel<<<blocks, 256>>>(h2, b2, out);
    }
}

// round 10
// speedup vs baseline: 3.6125x; 1.0356x over previous
#include <cuda_runtime.h>
#include <cuda_fp16.h>
#include <math.h>
#include <stdint.h>

#define N_NODES 100000
#define E_MAX   1600000
#define IN_DIM 128
#define HID 128
#define OUT_DIM 64
#define NB ((N_NODES + 255) / 256)

// ---------------- scratch (device globals; no allocation allowed) -----------
__device__ __half g_h1[(size_t)N_NODES * HID];      // x @ W1  (fp16 storage)
__device__ float  g_hr[(size_t)N_NODES * HID];      // relu(aggregated layer1), fp32
__device__ __half g_h2[(size_t)N_NODES * OUT_DIM];  // hr @ W2 (fp16 storage)
__device__ float  g_dinv[N_NODES];
__device__ int    g_deg[N_NODES];
__device__ int    g_rowstart[N_NODES + 1];
__device__ int    g_cursor[N_NODES];
__device__ int    g_csr_src[E_MAX];
__device__ int    g_blocksum[NB];
__device__ int    g_blockoff[NB];

// ---------------- zero degree ------------------------------------------------
__global__ void zero_deg_kernel() {
    int i = blockIdx.x * blockDim.x + threadIdx.x;
    if (i < N_NODES) g_deg[i] = 0;
}

// ---------------- degree ------------------------------------------------------
__global__ void degree_kernel(const int* __restrict__ dst, int E) {
    int i = blockIdx.x * blockDim.x + threadIdx.x;
    if (i < E) atomicAdd(&g_deg[dst[i]], 1);
}

// ---------------- dinv --------------------------------------------------------
__global__ void dinv_kernel() {
    int v = blockIdx.x * blockDim.x + threadIdx.x;
    if (v < N_NODES) {
        float deg = (float)(g_deg[v] + 1);  // +1 self loop -> always > 0
        g_dinv[v] = rsqrtf(deg);
    }
}

// ---------------- 3-phase parallel exclusive scan of deg ---------------------
__global__ void scanA_kernel() {
    __shared__ int sh[256];
    int t = threadIdx.x;
    int idx = blockIdx.x * 256 + t;
    int d = (idx < N_NODES) ? g_deg[idx] : 0;
    sh[t] = d;
    __syncthreads();
#pragma unroll
    for (int off = 128; off > 0; off >>= 1) {
        if (t < off) sh[t] += sh[t + off];
        __syncthreads();
    }
    if (t == 0) g_blocksum[blockIdx.x] = sh[0];
}

__global__ void scanB_kernel() {
    __shared__ int sh[512];
    int t = threadIdx.x;
    int v = (t < NB) ? g_blocksum[t] : 0;
    sh[t] = v;
    __syncthreads();
    for (int off = 1; off < 512; off <<= 1) {
        int u = (t >= off) ? sh[t - off] : 0;
        __syncthreads();
        sh[t] += u;
        __syncthreads();
    }
    if (t < NB) g_blockoff[t] = sh[t] - v;  // exclusive block offset
    if (t == 511) g_rowstart[N_NODES] = sh[511];
}

__global__ void scanC_kernel() {
    __shared__ int sh[256];
    int t = threadIdx.x;
    int idx = blockIdx.x * 256 + t;
    int d = (idx < N_NODES) ? g_deg[idx] : 0;
    sh[t] = d;
    __syncthreads();
    for (int off = 1; off < 256; off <<= 1) {
        int u = (t >= off) ? sh[t - off] : 0;
        __syncthreads();
        sh[t] += u;
        __syncthreads();
    }
    if (idx < N_NODES) {
        int excl = g_blockoff[blockIdx.x] + sh[t] - d;
        g_rowstart[idx] = excl;
        g_cursor[idx] = excl;
    }
}

// ---------------- counting-sort fill: group edge srcs by dst ------------------
__global__ void fill_kernel(const int* __restrict__ src,
                            const int* __restrict__ dst, int E) {
    int i = blockIdx.x * blockDim.x + threadIdx.x;
    if (i < E) {
        int d = dst[i];
        int p = atomicAdd(&g_cursor[d], 1);
        g_csr_src[p] = src[i];
    }
}

// ---------------- SGEMM: C[M,N](fp16) = A[M,K=128](fp32) * B[128,N](fp32) ----
template <int N>
__global__ void __launch_bounds__(256) gemm_f16_kernel(
        const float* __restrict__ A,
        const float* __restrict__ B,
        __half* __restrict__ C, int M) {
    constexpr int K = 128;
    constexpr int BM = 64;
    constexpr int BK = 32;
    constexpr int TN = N / 32;  // 4 for N=128, 2 for N=64
    constexpr int TM = 8;

    __shared__ float As[BM][BK + 1];
    __shared__ float Bs[BK][N];

    int tid = threadIdx.x;
    int tx = tid & 31;
    int ty = tid >> 5;        // 0..7
    int row0 = blockIdx.x * BM;

    float acc[TM][TN];
#pragma unroll
    for (int i = 0; i < TM; i++)
#pragma unroll
        for (int j = 0; j < TN; j++) acc[i][j] = 0.0f;

    for (int k0 = 0; k0 < K; k0 += BK) {
#pragma unroll
        for (int l = 0; l < 8; l++) {
            int e = tid + l * 256;
            int r = e >> 5, c = e & 31;
            int gr = row0 + r;
            As[r][c] = (gr < M) ? A[(size_t)gr * K + k0 + c] : 0.0f;
        }
#pragma unroll
        for (int l = 0; l < (BK * N) / (256 * 4); l++) {
            int e = tid + l * 256;            // float4 index
            int r = e / (N / 4), c = e % (N / 4);
            ((float4*)&Bs[r][0])[c] = ((const float4*)&B[(size_t)(k0 + r) * N])[c];
        }
        __syncthreads();

#pragma unroll
        for (int kk = 0; kk < BK; kk++) {
            float a[TM];
#pragma unroll
            for (int i = 0; i < TM; i++) a[i] = As[ty * TM + i][kk];
            float b[TN];
            if (TN == 4) {
                float4 bv = ((const float4*)&Bs[kk][0])[tx];
                b[0] = bv.x; b[1] = bv.y; b[2] = bv.z; b[3] = bv.w;
            } else {
                float2 bv = ((const float2*)&Bs[kk][0])[tx];
                b[0] = bv.x; b[1] = bv.y;
            }
#pragma unroll
            for (int i = 0; i < TM; i++)
#pragma unroll
                for (int j = 0; j < TN; j++) acc[i][j] += a[i] * b[j];
        }
        __syncthreads();
    }

#pragma unroll
    for (int i = 0; i < TM; i++) {
        int gr = row0 + ty * TM + i;
        if (gr < M) {
            if (TN == 4) {
                __half2 p0 = __floats2half2_rn(acc[i][0], acc[i][1]);
                __half2 p1 = __floats2half2_rn(acc[i][2], acc[i][3]);
                uint2 o;
                o.x = *(unsigned int*)&p0;
                o.y = *(unsigned int*)&p1;
                ((uint2*)(C + (size_t)gr * N))[tx] = o;
            } else {
                __half2 p0 = __floats2half2_rn(acc[i][0], acc[i][1]);
                ((__half2*)(C + (size_t)gr * N))[tx] = p0;
            }
        }
    }
}

// helper: accumulate 8 fp16 (as uint4) * c into float acc[8]
__device__ __forceinline__ void acc_f16x8(float* acc, uint4 v, float c) {
    __half2 h0 = *(__half2*)&v.x;
    __half2 h1 = *(__half2*)&v.y;
    __half2 h2 = *(__half2*)&v.z;
    __half2 h3 = *(__half2*)&v.w;
    float2 f0 = __half22float2(h0);
    float2 f1 = __half22float2(h1);
    float2 f2 = __half22float2(h2);
    float2 f3 = __half22float2(h3);
    acc[0] += f0.x * c; acc[1] += f0.y * c;
    acc[2] += f1.x * c; acc[3] += f1.y * c;
    acc[4] += f2.x * c; acc[5] += f2.y * c;
    acc[6] += f3.x * c; acc[7] += f3.y * c;
}

// ---------------- layer1 pull-aggregation: 2 nodes/warp, LDG.128 -------------
// 16 lanes x uint4(16B) = 256B = 128 fp16 per row
__global__ void agg128_kernel(const __half* __restrict__ h,
                              const float* __restrict__ b1,
                              float* __restrict__ hr) {
    int gw = (blockIdx.x * blockDim.x + threadIdx.x) >> 5;
    int lane = threadIdx.x & 31;
    int halfid = lane >> 4;
    int sub = lane & 15;
    int v = gw * 2 + halfid;
    if (v >= N_NODES) return;

    int beg = g_rowstart[v];
    int end = g_rowstart[v + 1];

    float acc[8];
#pragma unroll
    for (int j = 0; j < 8; j++) acc[j] = 0.f;

    int e = beg;
    for (; e + 4 <= end; e += 4) {
        int   sx[4];
        float cx[4];
#pragma unroll
        for (int q = 0; q < 4; q++) sx[q] = g_csr_src[e + q];
#pragma unroll
        for (int q = 0; q < 4; q++) cx[q] = g_dinv[sx[q]];
        uint4 vv[4];
#pragma unroll
        for (int q = 0; q < 4; q++)
            vv[q] = ((const uint4*)(h + (size_t)sx[q] * 128))[sub];
#pragma unroll
        for (int q = 0; q < 4; q++) acc_f16x8(acc, vv[q], cx[q]);
    }
    for (; e < end; e++) {
        int s0 = g_csr_src[e];
        float c0 = g_dinv[s0];
        uint4 v0 = ((const uint4*)(h + (size_t)s0 * 128))[sub];
        acc_f16x8(acc, v0, c0);
    }

    float dv = g_dinv[v];
    uint4 sv = ((const uint4*)(h + (size_t)v * 128))[sub];
    acc_f16x8(acc, sv, dv);  // self-loop term
    float4 b0 = ((const float4*)b1)[sub * 2];
    float4 b1v = ((const float4*)b1)[sub * 2 + 1];
    float4 r0, r1;
    r0.x = fmaxf(acc[0] * dv + b0.x, 0.f);
    r0.y = fmaxf(acc[1] * dv + b0.y, 0.f);
    r0.z = fmaxf(acc[2] * dv + b0.z, 0.f);
    r0.w = fmaxf(acc[3] * dv + b0.w, 0.f);
    r1.x = fmaxf(acc[4] * dv + b1v.x, 0.f);
    r1.y = fmaxf(acc[5] * dv + b1v.y, 0.f);
    r1.z = fmaxf(acc[6] * dv + b1v.z, 0.f);
    r1.w = fmaxf(acc[7] * dv + b1v.w, 0.f);
    ((float4*)(hr + (size_t)v * 128))[sub * 2] = r0;
    ((float4*)(hr + (size_t)v * 128))[sub * 2 + 1] = r1;
}

// ---------------- layer2 pull-aggregation + log_softmax ----------------------
// 4 nodes/warp: 8 lanes x uint4(16B) = 128B = 64 fp16 per row
__global__ void agg64_final_kernel(const __half* __restrict__ h,
                                   const float* __restrict__ b2,
                                   float* __restrict__ out) {
    int gw = (blockIdx.x * blockDim.x + threadIdx.x) >> 5;
    int lane = threadIdx.x & 31;
    int quad = lane >> 3;
    int sub = lane & 7;
    int v = gw * 4 + quad;
    if (v >= N_NODES) return;

    int beg = g_rowstart[v];
    int end = g_rowstart[v + 1];

    float acc[8];
#pragma unroll
    for (int j = 0; j < 8; j++) acc[j] = 0.f;

    int e = beg;
    for (; e + 4 <= end; e += 4) {
        int   sx[4];
        float cx[4];
#pragma unroll
        for (int q = 0; q < 4; q++) sx[q] = g_csr_src[e + q];
#pragma unroll
        for (int q = 0; q < 4; q++) cx[q] = g_dinv[sx[q]];
        uint4 vv[4];
#pragma unroll
        for (int q = 0; q < 4; q++)
            vv[q] = ((const uint4*)(h + (size_t)sx[q] * 64))[sub];
#pragma unroll
        for (int q = 0; q < 4; q++) acc_f16x8(acc, vv[q], cx[q]);
    }
    for (; e < end; e++) {
        int s0 = g_csr_src[e];
        float c0 = g_dinv[s0];
        uint4 v0 = ((const uint4*)(h + (size_t)s0 * 64))[sub];
        acc_f16x8(acc, v0, c0);
    }

    float dv = g_dinv[v];
    uint4 sv = ((const uint4*)(h + (size_t)v * 64))[sub];
    acc_f16x8(acc, sv, dv);
    float4 b0 = ((const float4*)b2)[sub * 2];
    float4 b1v = ((const float4*)b2)[sub * 2 + 1];
    float t[8];
    t[0] = acc[0] * dv + b0.x;
    t[1] = acc[1] * dv + b0.y;
    t[2] = acc[2] * dv + b0.z;
    t[3] = acc[3] * dv + b0.w;
    t[4] = acc[4] * dv + b1v.x;
    t[5] = acc[5] * dv + b1v.y;
    t[6] = acc[6] * dv + b1v.z;
    t[7] = acc[7] * dv + b1v.w;

    float m = t[0];
#pragma unroll
    for (int j = 1; j < 8; j++) m = fmaxf(m, t[j]);
#pragma unroll
    for (int o = 4; o > 0; o >>= 1)
        m = fmaxf(m, __shfl_xor_sync(0xFFFFFFFF, m, o));
    float s = 0.f;
#pragma unroll
    for (int j = 0; j < 8; j++) s += __expf(t[j] - m);
#pragma unroll
    for (int o = 4; o > 0; o >>= 1)
        s += __shfl_xor_sync(0xFFFFFFFF, s, o);
    float lse = m + logf(s);
    float4 r0 = make_float4(t[0] - lse, t[1] - lse, t[2] - lse, t[3] - lse);
    float4 r1 = make_float4(t[4] - lse, t[5] - lse, t[6] - lse, t[7] - lse);
    ((float4*)(out + (size_t)v * 64))[sub * 2] = r0;
    ((float4*)(out + (size_t)v * 64))[sub * 2 + 1] = r1;
}

// ---------------- host-side stream/event handles (host objects only) ---------
struct HostRes {
    cudaStream_t s2;
    cudaEvent_t ev_fork, ev_join;
    HostRes() {
        cudaStreamCreateWithFlags(&s2, cudaStreamNonBlocking);
        cudaEventCreateWithFlags(&ev_fork, cudaEventDisableTiming);
        cudaEventCreateWithFlags(&ev_join, cudaEventDisableTiming);
    }
};

// ---------------- launch ------------------------------------------------------
extern "C" void kernel_launch(void* const* d_in, const int* in_sizes, int n_in,
                              void* d_out, int out_size) {
    const float* x = (const float*)d_in[0];
    const int* ei = (const int*)d_in[1];
    const float* W1 = (const float*)d_in[2];
    const float* b1 = (const float*)d_in[3];
    const float* W2 = (const float*)d_in[4];
    const float* b2 = (const float*)d_in[5];
    float* out = (float*)d_out;

    int E = in_sizes[1] / 2;
    const int* src = ei;
    const int* dst = ei + E;

    __half* h1; cudaGetSymbolAddress((void**)&h1, g_h1);
    float*  hr; cudaGetSymbolAddress((void**)&hr, g_hr);
    __half* h2; cudaGetSymbolAddress((void**)&h2, g_h2);

    static HostRes R;  // host handles only; device work identical every call

    // fork: GEMM1 (depends only on x,W1) runs on R.s2 concurrently with CSR prep
    cudaEventRecord(R.ev_fork, 0);
    cudaStreamWaitEvent(R.s2, R.ev_fork, 0);
    gemm_f16_kernel<HID><<<(N_NODES + 63) / 64, 256, 0, R.s2>>>(x, W1, h1, N_NODES);
    cudaEventRecord(R.ev_join, R.s2);

    // CSR prep on the capture stream (no fp atomics anywhere)
    zero_deg_kernel<<<(N_NODES + 255) / 256, 256>>>();
    degree_kernel<<<(E + 255) / 256, 256>>>(dst, E);
    scanA_kernel<<<NB, 256>>>();
    scanB_kernel<<<1, 512>>>();
    scanC_kernel<<<NB, 256>>>();
    dinv_kernel<<<(N_NODES + 255) / 256, 256>>>();
    fill_kernel<<<(E + 255) / 256, 256>>>(src, dst, E);

    // join before aggregation needs h1
    cudaStreamWaitEvent(0, R.ev_join, 0);

    // layer 1 aggregate (+bias+relu fused): 2 nodes per warp
    {
        long long warps = (N_NODES + 1) / 2;
        long long threads = warps * 32;
        int blocks = (int)((threads + 255) / 256);
        agg128_kernel<<<blocks, 256>>>(h1, b1, hr);
    }

    // layer 2: transform then aggregate (+bias+log_softmax fused): 4 nodes/warp
    gemm_f16_kernel<OUT_DIM><<<(N_NODES + 63) / 64, 256>>>(hr, W2, h2, N_NODES);
    {
        long long warps = (N_NODES + 3) / 4;
        long long threads = warps * 32;
        int blocks = (int)((threads + 255) / 256);
        agg64_final_kernel<<<blocks, 256>>>(h2, b2, out);
    }
}

// round 11
// speedup vs baseline: 4.4523x; 1.2325x over previous
#include <cuda_runtime.h>
#include <cuda_fp16.h>
#include <mma.h>
#include <math.h>
#include <stdint.h>

using namespace nvcuda;

#define N_NODES 100000
#define E_MAX   1600000
#define IN_DIM 128
#define HID 128
#define OUT_DIM 64
#define NB ((N_NODES + 255) / 256)

// ---------------- scratch (device globals; no allocation allowed) -----------
__device__ __half g_h1[(size_t)N_NODES * HID];      // x @ W1  (fp16 storage)
__device__ float  g_hr[(size_t)N_NODES * HID];      // relu(aggregated layer1), fp32
__device__ __half g_h2[(size_t)N_NODES * OUT_DIM];  // hr @ W2 (fp16 storage)
__device__ float  g_dinv[N_NODES];
__device__ int    g_deg[N_NODES];
__device__ int    g_rowstart[N_NODES + 1];
__device__ int    g_cursor[N_NODES];
__device__ int    g_csr_src[E_MAX];
__device__ int    g_blocksum[NB];
__device__ int    g_blockoff[NB];

// ---------------- zero degree ------------------------------------------------
__global__ void zero_deg_kernel() {
    int i = blockIdx.x * blockDim.x + threadIdx.x;
    if (i < N_NODES) g_deg[i] = 0;
}

// ---------------- degree ------------------------------------------------------
__global__ void degree_kernel(const int* __restrict__ dst, int E) {
    int i = blockIdx.x * blockDim.x + threadIdx.x;
    if (i < E) atomicAdd(&g_deg[dst[i]], 1);
}

// ---------------- 3-phase parallel exclusive scan of deg (+ dinv fused) ------
__global__ void scanA_kernel() {
    __shared__ int sh[256];
    int t = threadIdx.x;
    int idx = blockIdx.x * 256 + t;
    int d = (idx < N_NODES) ? g_deg[idx] : 0;
    if (idx < N_NODES) g_dinv[idx] = rsqrtf((float)(d + 1));  // fused dinv
    sh[t] = d;
    __syncthreads();
#pragma unroll
    for (int off = 128; off > 0; off >>= 1) {
        if (t < off) sh[t] += sh[t + off];
        __syncthreads();
    }
    if (t == 0) g_blocksum[blockIdx.x] = sh[0];
}

__global__ void scanB_kernel() {
    __shared__ int sh[512];
    int t = threadIdx.x;
    int v = (t < NB) ? g_blocksum[t] : 0;
    sh[t] = v;
    __syncthreads();
    for (int off = 1; off < 512; off <<= 1) {
        int u = (t >= off) ? sh[t - off] : 0;
        __syncthreads();
        sh[t] += u;
        __syncthreads();
    }
    if (t < NB) g_blockoff[t] = sh[t] - v;  // exclusive block offset
    if (t == 511) g_rowstart[N_NODES] = sh[511];
}

__global__ void scanC_kernel() {
    __shared__ int sh[256];
    int t = threadIdx.x;
    int idx = blockIdx.x * 256 + t;
    int d = (idx < N_NODES) ? g_deg[idx] : 0;
    sh[t] = d;
    __syncthreads();
    for (int off = 1; off < 256; off <<= 1) {
        int u = (t >= off) ? sh[t - off] : 0;
        __syncthreads();
        sh[t] += u;
        __syncthreads();
    }
    if (idx < N_NODES) {
        int excl = g_blockoff[blockIdx.x] + sh[t] - d;
        g_rowstart[idx] = excl;
        g_cursor[idx] = excl;
    }
}

// ---------------- counting-sort fill: group edge srcs by dst ------------------
__global__ void fill_kernel(const int* __restrict__ src,
                            const int* __restrict__ dst, int E) {
    int i = blockIdx.x * blockDim.x + threadIdx.x;
    if (i < E) {
        int d = dst[i];
        int p = atomicAdd(&g_cursor[d], 1);
        g_csr_src[p] = src[i];
    }
}

// ---------------- WMMA GEMM: C[M,N](fp16) = A[M,128](fp32) * B[128,N](fp32) --
// BM=64 rows/block, 256 threads = 8 warps. fp16 inputs (converted in smem),
// fp32 accumulate, fp16 output. Warp grid: 4 (m) x 2 (n halves).
template <int N>
__global__ void __launch_bounds__(256) gemm_wmma_kernel(
        const float* __restrict__ A,
        const float* __restrict__ B,
        __half* __restrict__ C, int M) {
    constexpr int K = 128;
    constexpr int BM = 64;
    constexpr int LDA = K + 8;       // 136, mult of 8
    constexpr int LDB = N + 8;       // 136 / 72, mult of 8
    constexpr int NT = N / 32;       // n-tiles of 16 per warp: 4 for 128, 2 for 64
    constexpr size_t AS_BYTES = (size_t)BM * LDA * 2;         // 17408
    constexpr size_t BS_BYTES = (size_t)K * LDB * 2;          // 34816 / 18432

    extern __shared__ char smem[];
    __half* As = (__half*)smem;
    __half* Bs = (__half*)(smem + AS_BYTES);
    float*  Cs = (float*)(smem + AS_BYTES + BS_BYTES);        // BM x N

    int tid = threadIdx.x;
    int wid = tid >> 5;
    int row0 = blockIdx.x * BM;

    // load + convert A tile: BM*K = 8192 elems, 32/thread, coalesced
#pragma unroll
    for (int l = 0; l < (BM * K) / 256; l++) {
        int e = tid + l * 256;
        int r = e >> 7, c = e & 127;
        int gr = row0 + r;
        As[r * LDA + c] = (gr < M) ? __float2half(A[(size_t)gr * K + c])
                                   : __half(0.0f);
    }
    // load + convert B (the whole weight): K*N elems
#pragma unroll
    for (int l = 0; l < (K * N) / 256; l++) {
        int e = tid + l * 256;
        int r = e / N, c = e % N;
        Bs[r * LDB + c] = __float2half(B[(size_t)r * N + c]);
    }
    __syncthreads();

    int m0 = (wid & 3) * 16;                 // 4 m-tiles cover 64 rows
    int n_off = (wid >> 2) * (N / 2);        // 2 n-halves

    wmma::fragment<wmma::accumulator, 16, 16, 16, float> cf[NT];
#pragma unroll
    for (int j = 0; j < NT; j++) wmma::fill_fragment(cf[j], 0.0f);

#pragma unroll
    for (int k0 = 0; k0 < K; k0 += 16) {
        wmma::fragment<wmma::matrix_a, 16, 16, 16, __half, wmma::row_major> af;
        wmma::load_matrix_sync(af, &As[m0 * LDA + k0], LDA);
#pragma unroll
        for (int j = 0; j < NT; j++) {
            wmma::fragment<wmma::matrix_b, 16, 16, 16, __half, wmma::row_major> bf;
            wmma::load_matrix_sync(bf, &Bs[k0 * LDB + n_off + j * 16], LDB);
            wmma::mma_sync(cf[j], af, bf, cf[j]);
        }
    }

    // stage fp32 C in smem, then convert to fp16 global
#pragma unroll
    for (int j = 0; j < NT; j++)
        wmma::store_matrix_sync(&Cs[m0 * N + n_off + j * 16], cf[j], N,
                                wmma::mem_row_major);
    __syncthreads();

#pragma unroll
    for (int l = 0; l < (BM * N / 2) / 256; l++) {
        int e = tid + l * 256;                 // half2 index
        int r = e / (N / 2), c2 = e % (N / 2);
        int gr = row0 + r;
        if (gr < M) {
            float2 f = ((const float2*)&Cs[r * N])[c2];
            ((__half2*)(C + (size_t)gr * N))[c2] = __floats2half2_rn(f.x, f.y);
        }
    }
}

// helper: accumulate 8 fp16 (as uint4) * c into float acc[8]
__device__ __forceinline__ void acc_f16x8(float* acc, uint4 v, float c) {
    __half2 h0 = *(__half2*)&v.x;
    __half2 h1 = *(__half2*)&v.y;
    __half2 h2 = *(__half2*)&v.z;
    __half2 h3 = *(__half2*)&v.w;
    float2 f0 = __half22float2(h0);
    float2 f1 = __half22float2(h1);
    float2 f2 = __half22float2(h2);
    float2 f3 = __half22float2(h3);
    acc[0] += f0.x * c; acc[1] += f0.y * c;
    acc[2] += f1.x * c; acc[3] += f1.y * c;
    acc[4] += f2.x * c; acc[5] += f2.y * c;
    acc[6] += f3.x * c; acc[7] += f3.y * c;
}

// ---------------- layer1 pull-aggregation: 2 nodes/warp, LDG.128 -------------
__global__ void agg128_kernel(const __half* __restrict__ h,
                              const float* __restrict__ b1,
                              float* __restrict__ hr) {
    int gw = (blockIdx.x * blockDim.x + threadIdx.x) >> 5;
    int lane = threadIdx.x & 31;
    int halfid = lane >> 4;
    int sub = lane & 15;
    int v = gw * 2 + halfid;
    if (v >= N_NODES) return;

    int beg = g_rowstart[v];
    int end = g_rowstart[v + 1];

    float acc[8];
#pragma unroll
    for (int j = 0; j < 8; j++) acc[j] = 0.f;

    int e = beg;
    for (; e + 4 <= end; e += 4) {
        int   sx[4];
        float cx[4];
#pragma unroll
        for (int q = 0; q < 4; q++) sx[q] = g_csr_src[e + q];
#pragma unroll
        for (int q = 0; q < 4; q++) cx[q] = g_dinv[sx[q]];
        uint4 vv[4];
#pragma unroll
        for (int q = 0; q < 4; q++)
            vv[q] = ((const uint4*)(h + (size_t)sx[q] * 128))[sub];
#pragma unroll
        for (int q = 0; q < 4; q++) acc_f16x8(acc, vv[q], cx[q]);
    }
    for (; e < end; e++) {
        int s0 = g_csr_src[e];
        float c0 = g_dinv[s0];
        uint4 v0 = ((const uint4*)(h + (size_t)s0 * 128))[sub];
        acc_f16x8(acc, v0, c0);
    }

    float dv = g_dinv[v];
    uint4 sv = ((const uint4*)(h + (size_t)v * 128))[sub];
    acc_f16x8(acc, sv, dv);  // self-loop term
    float4 b0 = ((const float4*)b1)[sub * 2];
    float4 b1v = ((const float4*)b1)[sub * 2 + 1];
    float4 r0, r1;
    r0.x = fmaxf(acc[0] * dv + b0.x, 0.f);
    r0.y = fmaxf(acc[1] * dv + b0.y, 0.f);
    r0.z = fmaxf(acc[2] * dv + b0.z, 0.f);
    r0.w = fmaxf(acc[3] * dv + b0.w, 0.f);
    r1.x = fmaxf(acc[4] * dv + b1v.x, 0.f);
    r1.y = fmaxf(acc[5] * dv + b1v.y, 0.f);
    r1.z = fmaxf(acc[6] * dv + b1v.z, 0.f);
    r1.w = fmaxf(acc[7] * dv + b1v.w, 0.f);
    ((float4*)(hr + (size_t)v * 128))[sub * 2] = r0;
    ((float4*)(hr + (size_t)v * 128))[sub * 2 + 1] = r1;
}

// ---------------- layer2 pull-aggregation + log_softmax ----------------------
__global__ void agg64_final_kernel(const __half* __restrict__ h,
                                   const float* __restrict__ b2,
                                   float* __restrict__ out) {
    int gw = (blockIdx.x * blockDim.x + threadIdx.x) >> 5;
    int lane = threadIdx.x & 31;
    int quad = lane >> 3;
    int sub = lane & 7;
    int v = gw * 4 + quad;
    if (v >= N_NODES) return;

    int beg = g_rowstart[v];
    int end = g_rowstart[v + 1];

    float acc[8];
#pragma unroll
    for (int j = 0; j < 8; j++) acc[j] = 0.f;

    int e = beg;
    for (; e + 4 <= end; e += 4) {
        int   sx[4];
        float cx[4];
#pragma unroll
        for (int q = 0; q < 4; q++) sx[q] = g_csr_src[e + q];
#pragma unroll
        for (int q = 0; q < 4; q++) cx[q] = g_dinv[sx[q]];
        uint4 vv[4];
#pragma unroll
        for (int q = 0; q < 4; q++)
            vv[q] = ((const uint4*)(h + (size_t)sx[q] * 64))[sub];
#pragma unroll
        for (int q = 0; q < 4; q++) acc_f16x8(acc, vv[q], cx[q]);
    }
    for (; e < end; e++) {
        int s0 = g_csr_src[e];
        float c0 = g_dinv[s0];
        uint4 v0 = ((const uint4*)(h + (size_t)s0 * 64))[sub];
        acc_f16x8(acc, v0, c0);
    }

    float dv = g_dinv[v];
    uint4 sv = ((const uint4*)(h + (size_t)v * 64))[sub];
    acc_f16x8(acc, sv, dv);
    float4 b0 = ((const float4*)b2)[sub * 2];
    float4 b1v = ((const float4*)b2)[sub * 2 + 1];
    float t[8];
    t[0] = acc[0] * dv + b0.x;
    t[1] = acc[1] * dv + b0.y;
    t[2] = acc[2] * dv + b0.z;
    t[3] = acc[3] * dv + b0.w;
    t[4] = acc[4] * dv + b1v.x;
    t[5] = acc[5] * dv + b1v.y;
    t[6] = acc[6] * dv + b1v.z;
    t[7] = acc[7] * dv + b1v.w;

    float m = t[0];
#pragma unroll
    for (int j = 1; j < 8; j++) m = fmaxf(m, t[j]);
#pragma unroll
    for (int o = 4; o > 0; o >>= 1)
        m = fmaxf(m, __shfl_xor_sync(0xFFFFFFFF, m, o));
    float s = 0.f;
#pragma unroll
    for (int j = 0; j < 8; j++) s += __expf(t[j] - m);
#pragma unroll
    for (int o = 4; o > 0; o >>= 1)
        s += __shfl_xor_sync(0xFFFFFFFF, s, o);
    float lse = m + logf(s);
    float4 r0 = make_float4(t[0] - lse, t[1] - lse, t[2] - lse, t[3] - lse);
    float4 r1 = make_float4(t[4] - lse, t[5] - lse, t[6] - lse, t[7] - lse);
    ((float4*)(out + (size_t)v * 64))[sub * 2] = r0;
    ((float4*)(out + (size_t)v * 64))[sub * 2 + 1] = r1;
}

// ---------------- host-side stream/event handles (host objects only) ---------
struct HostRes {
    cudaStream_t s2;
    cudaEvent_t ev_fork, ev_join;
    HostRes() {
        cudaStreamCreateWithFlags(&s2, cudaStreamNonBlocking);
        cudaEventCreateWithFlags(&ev_fork, cudaEventDisableTiming);
        cudaEventCreateWithFlags(&ev_join, cudaEventDisableTiming);
        // dynamic smem opt-in (one-time, host-side attribute set)
        cudaFuncSetAttribute(gemm_wmma_kernel<HID>,
                             cudaFuncAttributeMaxDynamicSharedMemorySize, 85000);
        cudaFuncSetAttribute(gemm_wmma_kernel<OUT_DIM>,
                             cudaFuncAttributeMaxDynamicSharedMemorySize, 53000);
    }
};

// smem sizes: As(64*136*2) + Bs(128*(N+8)*2) + Cs(64*N*4)
static constexpr size_t SMEM_G128 = 17408 + 34816 + 32768;  // 84992
static constexpr size_t SMEM_G64  = 17408 + 18432 + 16384;  // 52224

// ---------------- launch ------------------------------------------------------
extern "C" void kernel_launch(void* const* d_in, const int* in_sizes, int n_in,
                              void* d_out, int out_size) {
    const float* x = (const float*)d_in[0];
    const int* ei = (const int*)d_in[1];
    const float* W1 = (const float*)d_in[2];
    const float* b1 = (const float*)d_in[3];
    const float* W2 = (const float*)d_in[4];
    const float* b2 = (const float*)d_in[5];
    float* out = (float*)d_out;

    int E = in_sizes[1] / 2;
    const int* src = ei;
    const int* dst = ei + E;

    __half* h1; cudaGetSymbolAddress((void**)&h1, g_h1);
    float*  hr; cudaGetSymbolAddress((void**)&hr, g_hr);
    __half* h2; cudaGetSymbolAddress((void**)&h2, g_h2);

    static HostRes R;  // host handles only; device work identical every call

    // fork: GEMM1 (depends only on x,W1) runs on R.s2 concurrently with CSR prep
    cudaEventRecord(R.ev_fork, 0);
    cudaStreamWaitEvent(R.s2, R.ev_fork, 0);
    gemm_wmma_kernel<HID><<<(N_NODES + 63) / 64, 256, SMEM_G128, R.s2>>>(
        x, W1, h1, N_NODES);
    cudaEventRecord(R.ev_join, R.s2);

    // CSR prep on the capture stream (no fp atomics anywhere)
    zero_deg_kernel<<<(N_NODES + 255) / 256, 256>>>();
    degree_kernel<<<(E + 255) / 256, 256>>>(dst, E);
    scanA_kernel<<<NB, 256>>>();          // also computes dinv
    scanB_kernel<<<1, 512>>>();
    scanC_kernel<<<NB, 256>>>();
    fill_kernel<<<(E + 255) / 256, 256>>>(src, dst, E);

    // join before aggregation needs h1
    cudaStreamWaitEvent(0, R.ev_join, 0);

    // layer 1 aggregate (+bias+relu fused): 2 nodes per warp
    {
        long long warps = (N_NODES + 1) / 2;
        long long threads = warps * 32;
        int blocks = (int)((threads + 255) / 256);
        agg128_kernel<<<blocks, 256>>>(h1, b1, hr);
    }

    // layer 2: transform then aggregate (+bias+log_softmax fused): 4 nodes/warp
    gemm_wmma_kernel<OUT_DIM><<<(N_NODES + 63) / 64, 256, SMEM_G64>>>(
        hr, W2, h2, N_NODES);
    {
        long long warps = (N_NODES + 3) / 4;
        long long threads = warps * 32;
        int blocks = (int)((threads + 255) / 256);
        agg64_final_kernel<<<blocks, 256>>>(h2, b2, out);
    }
}

// round 12
// speedup vs baseline: 4.7241x; 1.0610x over previous
#include <cuda_runtime.h>
#include <cuda_fp16.h>
#include <mma.h>
#include <math.h>
#include <stdint.h>

using namespace nvcuda;

#define N_NODES 100000
#define E_MAX   1600000
#define IN_DIM 128
#define HID 128
#define OUT_DIM 64
#define NB ((N_NODES + 255) / 256)

// ---------------- scratch (device globals; no allocation allowed) -----------
__device__ __half g_h1[(size_t)N_NODES * HID];      // x @ W1  (fp16)
__device__ __half g_hr[(size_t)N_NODES * HID];      // relu(agg layer1) (fp16)
__device__ __half g_h2[(size_t)N_NODES * OUT_DIM];  // hr @ W2 (fp16)
__device__ float  g_dinv[N_NODES];
__device__ int    g_deg[N_NODES];
__device__ int    g_rowstart[N_NODES + 1];
__device__ int    g_cursor[N_NODES];
__device__ uint2  g_csr[E_MAX];                     // {src, coef bits (fp32)}
__device__ int    g_blocksum[NB];
__device__ int    g_blockoff[NB];

// ---------------- zero degree ------------------------------------------------
__global__ void zero_deg_kernel() {
    int i = blockIdx.x * blockDim.x + threadIdx.x;
    if (i < N_NODES) g_deg[i] = 0;
}

// ---------------- degree ------------------------------------------------------
__global__ void degree_kernel(const int* __restrict__ dst, int E) {
    int i = blockIdx.x * blockDim.x + threadIdx.x;
    if (i < E) atomicAdd(&g_deg[dst[i]], 1);
}

// ---------------- 3-phase parallel exclusive scan of deg (+ dinv fused) ------
__global__ void scanA_kernel() {
    __shared__ int sh[256];
    int t = threadIdx.x;
    int idx = blockIdx.x * 256 + t;
    int d = (idx < N_NODES) ? g_deg[idx] : 0;
    if (idx < N_NODES) g_dinv[idx] = rsqrtf((float)(d + 1));  // fused dinv
    sh[t] = d;
    __syncthreads();
#pragma unroll
    for (int off = 128; off > 0; off >>= 1) {
        if (t < off) sh[t] += sh[t + off];
        __syncthreads();
    }
    if (t == 0) g_blocksum[blockIdx.x] = sh[0];
}

__global__ void scanB_kernel() {
    __shared__ int sh[512];
    int t = threadIdx.x;
    int v = (t < NB) ? g_blocksum[t] : 0;
    sh[t] = v;
    __syncthreads();
    for (int off = 1; off < 512; off <<= 1) {
        int u = (t >= off) ? sh[t - off] : 0;
        __syncthreads();
        sh[t] += u;
        __syncthreads();
    }
    if (t < NB) g_blockoff[t] = sh[t] - v;  // exclusive block offset
    if (t == 511) g_rowstart[N_NODES] = sh[511];
}

__global__ void scanC_kernel() {
    __shared__ int sh[256];
    int t = threadIdx.x;
    int idx = blockIdx.x * 256 + t;
    int d = (idx < N_NODES) ? g_deg[idx] : 0;
    sh[t] = d;
    __syncthreads();
    for (int off = 1; off < 256; off <<= 1) {
        int u = (t >= off) ? sh[t - off] : 0;
        __syncthreads();
        sh[t] += u;
        __syncthreads();
    }
    if (idx < N_NODES) {
        int excl = g_blockoff[blockIdx.x] + sh[t] - d;
        g_rowstart[idx] = excl;
        g_cursor[idx] = excl;
    }
}

// ---------------- counting-sort fill: {src, dinv[src]} grouped by dst --------
__global__ void fill_kernel(const int* __restrict__ src,
                            const int* __restrict__ dst, int E) {
    int i = blockIdx.x * blockDim.x + threadIdx.x;
    if (i < E) {
        int s = src[i];
        int d = dst[i];
        float c = g_dinv[s];
        int p = atomicAdd(&g_cursor[d], 1);
        g_csr[p] = make_uint2((unsigned)s, __float_as_uint(c));
    }
}

// ---------------- WMMA GEMM: C[M,N](fp16) = A[M,128](TA) * B[128,N](fp32) ----
// BM=64 rows/block, 256 threads = 8 warps. fp16 operands in smem, fp32 accum.
template <int N, typename TA>
__global__ void __launch_bounds__(256) gemm_wmma_kernel(
        const TA* __restrict__ A,
        const float* __restrict__ B,
        __half* __restrict__ C, int M) {
    constexpr int K = 128;
    constexpr int BM = 64;
    constexpr int LDA = K + 8;       // 136
    constexpr int LDB = N + 8;       // 136 / 72
    constexpr int NT = N / 32;       // 16-wide n-tiles per warp
    constexpr size_t AS_BYTES = (size_t)BM * LDA * 2;
    constexpr size_t BS_BYTES = (size_t)K * LDB * 2;

    extern __shared__ char smem[];
    __half* As = (__half*)smem;
    __half* Bs = (__half*)(smem + AS_BYTES);
    float*  Cs = (float*)(smem + AS_BYTES + BS_BYTES);  // BM x N

    int tid = threadIdx.x;
    int wid = tid >> 5;
    int row0 = blockIdx.x * BM;

    // stage A tile
    if constexpr (sizeof(TA) == 2) {
        // fp16 A: vectorized 8-wide copy. 8192/8 = 1024 uint4, 4 per thread.
#pragma unroll
        for (int l = 0; l < (BM * K / 8) / 256; l++) {
            int e = tid + l * 256;            // uint4 index
            int r = e >> 4, c8 = e & 15;      // 16 uint4 per row
            int gr = row0 + r;
            uint4 val = make_uint4(0u, 0u, 0u, 0u);
            if (gr < M)
                val = ((const uint4*)(A + (size_t)gr * K))[c8];
            *((uint4*)&As[r * LDA + c8 * 8]) = val;
        }
    } else {
        // fp32 A: scalar convert
#pragma unroll
        for (int l = 0; l < (BM * K) / 256; l++) {
            int e = tid + l * 256;
            int r = e >> 7, c = e & 127;
            int gr = row0 + r;
            As[r * LDA + c] = (gr < M) ? __float2half(((const float*)A)[(size_t)gr * K + c])
                                       : __half(0.0f);
        }
    }
    // stage B (whole weight), fp32 -> fp16
#pragma unroll
    for (int l = 0; l < (K * N) / 256; l++) {
        int e = tid + l * 256;
        int r = e / N, c = e % N;
        Bs[r * LDB + c] = __float2half(B[(size_t)r * N + c]);
    }
    __syncthreads();

    int m0 = (wid & 3) * 16;
    int n_off = (wid >> 2) * (N / 2);

    wmma::fragment<wmma::accumulator, 16, 16, 16, float> cf[NT];
#pragma unroll
    for (int j = 0; j < NT; j++) wmma::fill_fragment(cf[j], 0.0f);

#pragma unroll
    for (int k0 = 0; k0 < K; k0 += 16) {
        wmma::fragment<wmma::matrix_a, 16, 16, 16, __half, wmma::row_major> af;
        wmma::load_matrix_sync(af, &As[m0 * LDA + k0], LDA);
#pragma unroll
        for (int j = 0; j < NT; j++) {
            wmma::fragment<wmma::matrix_b, 16, 16, 16, __half, wmma::row_major> bf;
            wmma::load_matrix_sync(bf, &Bs[k0 * LDB + n_off + j * 16], LDB);
            wmma::mma_sync(cf[j], af, bf, cf[j]);
        }
    }

#pragma unroll
    for (int j = 0; j < NT; j++)
        wmma::store_matrix_sync(&Cs[m0 * N + n_off + j * 16], cf[j], N,
                                wmma::mem_row_major);
    __syncthreads();

#pragma unroll
    for (int l = 0; l < (BM * N / 2) / 256; l++) {
        int e = tid + l * 256;                 // half2 index
        int r = e / (N / 2), c2 = e % (N / 2);
        int gr = row0 + r;
        if (gr < M) {
            float2 f = ((const float2*)&Cs[r * N])[c2];
            ((__half2*)(C + (size_t)gr * N))[c2] = __floats2half2_rn(f.x, f.y);
        }
    }
}

// helper: accumulate 8 fp16 (as uint4) * c into float acc[8]
__device__ __forceinline__ void acc_f16x8(float* acc, uint4 v, float c) {
    __half2 h0 = *(__half2*)&v.x;
    __half2 h1 = *(__half2*)&v.y;
    __half2 h2 = *(__half2*)&v.z;
    __half2 h3 = *(__half2*)&v.w;
    float2 f0 = __half22float2(h0);
    float2 f1 = __half22float2(h1);
    float2 f2 = __half22float2(h2);
    float2 f3 = __half22float2(h3);
    acc[0] += f0.x * c; acc[1] += f0.y * c;
    acc[2] += f1.x * c; acc[3] += f1.y * c;
    acc[4] += f2.x * c; acc[5] += f2.y * c;
    acc[6] += f3.x * c; acc[7] += f3.y * c;
}

// ---------------- layer1 pull-aggregation: 2 nodes/warp, LDG.128 -------------
__global__ void agg128_kernel(const __half* __restrict__ h,
                              const float* __restrict__ b1,
                              __half* __restrict__ hr) {
    int gw = (blockIdx.x * blockDim.x + threadIdx.x) >> 5;
    int lane = threadIdx.x & 31;
    int halfid = lane >> 4;
    int sub = lane & 15;
    int v = gw * 2 + halfid;
    if (v >= N_NODES) return;

    int beg = g_rowstart[v];
    int end = g_rowstart[v + 1];

    float acc[8];
#pragma unroll
    for (int j = 0; j < 8; j++) acc[j] = 0.f;

    int e = beg;
    for (; e + 4 <= end; e += 4) {
        uint2 ec[4];
#pragma unroll
        for (int q = 0; q < 4; q++) ec[q] = g_csr[e + q];
        uint4 vv[4];
#pragma unroll
        for (int q = 0; q < 4; q++)
            vv[q] = ((const uint4*)(h + (size_t)ec[q].x * 128))[sub];
#pragma unroll
        for (int q = 0; q < 4; q++)
            acc_f16x8(acc, vv[q], __uint_as_float(ec[q].y));
    }
    for (; e < end; e++) {
        uint2 ec = g_csr[e];
        uint4 v0 = ((const uint4*)(h + (size_t)ec.x * 128))[sub];
        acc_f16x8(acc, v0, __uint_as_float(ec.y));
    }

    float dv = g_dinv[v];
    uint4 sv = ((const uint4*)(h + (size_t)v * 128))[sub];
    acc_f16x8(acc, sv, dv);  // self-loop term
    float4 b0 = ((const float4*)b1)[sub * 2];
    float4 b1v = ((const float4*)b1)[sub * 2 + 1];
    __half2 o[4];
    o[0] = __floats2half2_rn(fmaxf(acc[0] * dv + b0.x, 0.f),
                             fmaxf(acc[1] * dv + b0.y, 0.f));
    o[1] = __floats2half2_rn(fmaxf(acc[2] * dv + b0.z, 0.f),
                             fmaxf(acc[3] * dv + b0.w, 0.f));
    o[2] = __floats2half2_rn(fmaxf(acc[4] * dv + b1v.x, 0.f),
                             fmaxf(acc[5] * dv + b1v.y, 0.f));
    o[3] = __floats2half2_rn(fmaxf(acc[6] * dv + b1v.z, 0.f),
                             fmaxf(acc[7] * dv + b1v.w, 0.f));
    ((uint4*)(hr + (size_t)v * 128))[sub] = *(uint4*)o;
}

// ---------------- layer2 pull-aggregation + log_softmax ----------------------
__global__ void agg64_final_kernel(const __half* __restrict__ h,
                                   const float* __restrict__ b2,
                                   float* __restrict__ out) {
    int gw = (blockIdx.x * blockDim.x + threadIdx.x) >> 5;
    int lane = threadIdx.x & 31;
    int quad = lane >> 3;
    int sub = lane & 7;
    int v = gw * 4 + quad;
    if (v >= N_NODES) return;

    int beg = g_rowstart[v];
    int end = g_rowstart[v + 1];

    float acc[8];
#pragma unroll
    for (int j = 0; j < 8; j++) acc[j] = 0.f;

    int e = beg;
    for (; e + 4 <= end; e += 4) {
        uint2 ec[4];
#pragma unroll
        for (int q = 0; q < 4; q++) ec[q] = g_csr[e + q];
        uint4 vv[4];
#pragma unroll
        for (int q = 0; q < 4; q++)
            vv[q] = ((const uint4*)(h + (size_t)ec[q].x * 64))[sub];
#pragma unroll
        for (int q = 0; q < 4; q++)
            acc_f16x8(acc, vv[q], __uint_as_float(ec[q].y));
    }
    for (; e < end; e++) {
        uint2 ec = g_csr[e];
        uint4 v0 = ((const uint4*)(h + (size_t)ec.x * 64))[sub];
        acc_f16x8(acc, v0, __uint_as_float(ec.y));
    }

    float dv = g_dinv[v];
    uint4 sv = ((const uint4*)(h + (size_t)v * 64))[sub];
    acc_f16x8(acc, sv, dv);
    float4 b0 = ((const float4*)b2)[sub * 2];
    float4 b1v = ((const float4*)b2)[sub * 2 + 1];
    float t[8];
    t[0] = acc[0] * dv + b0.x;
    t[1] = acc[1] * dv + b0.y;
    t[2] = acc[2] * dv + b0.z;
    t[3] = acc[3] * dv + b0.w;
    t[4] = acc[4] * dv + b1v.x;
    t[5] = acc[5] * dv + b1v.y;
    t[6] = acc[6] * dv + b1v.z;
    t[7] = acc[7] * dv + b1v.w;

    float m = t[0];
#pragma unroll
    for (int j = 1; j < 8; j++) m = fmaxf(m, t[j]);
#pragma unroll
    for (int o = 4; o > 0; o >>= 1)
        m = fmaxf(m, __shfl_xor_sync(0xFFFFFFFF, m, o));
    float s = 0.f;
#pragma unroll
    for (int j = 0; j < 8; j++) s += __expf(t[j] - m);
#pragma unroll
    for (int o = 4; o > 0; o >>= 1)
        s += __shfl_xor_sync(0xFFFFFFFF, s, o);
    float lse = m + logf(s);
    float4 r0 = make_float4(t[0] - lse, t[1] - lse, t[2] - lse, t[3] - lse);
    float4 r1 = make_float4(t[4] - lse, t[5] - lse, t[6] - lse, t[7] - lse);
    ((float4*)(out + (size_t)v * 64))[sub * 2] = r0;
    ((float4*)(out + (size_t)v * 64))[sub * 2 + 1] = r1;
}

// ---------------- host-side stream/event handles (host objects only) ---------
struct HostRes {
    cudaStream_t s2;
    cudaEvent_t ev_fork, ev_join;
    HostRes() {
        cudaStreamCreateWithFlags(&s2, cudaStreamNonBlocking);
        cudaEventCreateWithFlags(&ev_fork, cudaEventDisableTiming);
        cudaEventCreateWithFlags(&ev_join, cudaEventDisableTiming);
        cudaFuncSetAttribute((const void*)gemm_wmma_kernel<HID, float>,
                             cudaFuncAttributeMaxDynamicSharedMemorySize, 85000);
        cudaFuncSetAttribute((const void*)gemm_wmma_kernel<OUT_DIM, __half>,
                             cudaFuncAttributeMaxDynamicSharedMemorySize, 53000);
    }
};

// smem sizes: As(64*136*2) + Bs(128*(N+8)*2) + Cs(64*N*4)
static constexpr size_t SMEM_G128 = 17408 + 34816 + 32768;  // 84992
static constexpr size_t SMEM_G64  = 17408 + 18432 + 16384;  // 52224

// ---------------- launch ------------------------------------------------------
extern "C" void kernel_launch(void* const* d_in, const int* in_sizes, int n_in,
                              void* d_out, int out_size) {
    const float* x = (const float*)d_in[0];
    const int* ei = (const int*)d_in[1];
    const float* W1 = (const float*)d_in[2];
    const float* b1 = (const float*)d_in[3];
    const float* W2 = (const float*)d_in[4];
    const float* b2 = (const float*)d_in[5];
    float* out = (float*)d_out;

    int E = in_sizes[1] / 2;
    const int* src = ei;
    const int* dst = ei + E;

    __half* h1; cudaGetSymbolAddress((void**)&h1, g_h1);
    __half* hr; cudaGetSymbolAddress((void**)&hr, g_hr);
    __half* h2; cudaGetSymbolAddress((void**)&h2, g_h2);

    static HostRes R;  // host handles only; device work identical every call

    // fork: GEMM1 (depends only on x,W1) runs on R.s2 concurrently with CSR prep
    cudaEventRecord(R.ev_fork, 0);
    cudaStreamWaitEvent(R.s2, R.ev_fork, 0);
    gemm_wmma_kernel<HID, float><<<(N_NODES + 63) / 64, 256, SMEM_G128, R.s2>>>(
        x, W1, h1, N_NODES);
    cudaEventRecord(R.ev_join, R.s2);

    // CSR prep on the capture stream (no fp atomics anywhere)
    zero_deg_kernel<<<(N_NODES + 255) / 256, 256>>>();
    degree_kernel<<<(E + 255) / 256, 256>>>(dst, E);
    scanA_kernel<<<NB, 256>>>();          // also computes dinv
    scanB_kernel<<<1, 512>>>();
    scanC_kernel<<<NB, 256>>>();
    fill_kernel<<<(E + 255) / 256, 256>>>(src, dst, E);

    // join before aggregation needs h1
    cudaStreamWaitEvent(0, R.ev_join, 0);

    // layer 1 aggregate (+bias+relu fused): 2 nodes per warp
    {
        long long warps = (N_NODES + 1) / 2;
        long long threads = warps * 32;
        int blocks = (int)((threads + 255) / 256);
        agg128_kernel<<<blocks, 256>>>(h1, b1, hr);
    }

    // layer 2: transform then aggregate (+bias+log_softmax fused): 4 nodes/warp
    gemm_wmma_kernel<OUT_DIM, __half><<<(N_NODES + 63) / 64, 256, SMEM_G64>>>(
        hr, W2, h2, N_NODES);
    {
        long long warps = (N_NODES + 3) / 4;
        long long threads = warps * 32;
        int blocks = (int)((threads + 255) / 256);
        agg64_final_kernel<<<blocks, 256>>>(h2, b2, out);
    }
}